// round 2
// baseline (speedup 1.0000x reference)
#include <cuda_runtime.h>
#include <cstdint>
#include <cstddef>

#define B_  4
#define T_  2048
#define C_  1024
#define H_  16
#define D_  64
#define M_  (B_ * T_)        // 8192
#define N3_ (3 * C_)         // 3072

// Scratch (static device globals — no allocation in kernel_launch)
__device__ __align__(16) float g_qkv[(size_t)M_ * N3_];   // [B*T, 3C]
__device__ __align__(16) float g_att[(size_t)M_ * C_];    // [B*T, C]

// ---------------------------------------------------------------------------
// SGEMM: C[M,N] = A[M,K] @ B[K,N], row-major, M%128==0, N%128==0, K%8==0
// 128x128 block tile, BK=8, 256 threads, 8x8 per thread (split 4+4 for
// conflict-free float4 shared reads).
// ---------------------------------------------------------------------------
__global__ __launch_bounds__(256, 2)
void sgemm128(const float* __restrict__ A, const float* __restrict__ Bm,
              float* __restrict__ Cm, int M, int N, int K) {
    __shared__ float As[8][128];   // [k][row]
    __shared__ float Bs[8][128];   // [k][col]

    const int tid = threadIdx.x;
    const int tx = tid & 15, ty = tid >> 4;
    const int rowBase = blockIdx.y << 7;
    const int colBase = blockIdx.x << 7;

    const int aRow = tid >> 1;             // 0..127
    const int aK4  = (tid & 1) << 2;       // 0 or 4
    const int bK   = tid >> 5;             // 0..7
    const int bC4  = (tid & 31) << 2;      // 0..124

    const float* Ap = A + (size_t)(rowBase + aRow) * K + aK4;
    const float* Bp = Bm + (size_t)bK * N + colBase + bC4;

    float acc[8][8];
#pragma unroll
    for (int i = 0; i < 8; i++)
#pragma unroll
        for (int j = 0; j < 8; j++) acc[i][j] = 0.f;

    for (int k0 = 0; k0 < K; k0 += 8) {
        float4 av = *(const float4*)Ap;
        float4 bv = *(const float4*)Bp;
        As[aK4 + 0][aRow] = av.x;
        As[aK4 + 1][aRow] = av.y;
        As[aK4 + 2][aRow] = av.z;
        As[aK4 + 3][aRow] = av.w;
        *(float4*)&Bs[bK][bC4] = bv;
        __syncthreads();

#pragma unroll
        for (int kk = 0; kk < 8; kk++) {
            float4 a0 = *(const float4*)&As[kk][ty * 4];
            float4 a1 = *(const float4*)&As[kk][64 + ty * 4];
            float4 b0 = *(const float4*)&Bs[kk][tx * 4];
            float4 b1 = *(const float4*)&Bs[kk][64 + tx * 4];
            float a[8] = {a0.x, a0.y, a0.z, a0.w, a1.x, a1.y, a1.z, a1.w};
            float b[8] = {b0.x, b0.y, b0.z, b0.w, b1.x, b1.y, b1.z, b1.w};
#pragma unroll
            for (int i = 0; i < 8; i++)
#pragma unroll
                for (int j = 0; j < 8; j++)
                    acc[i][j] = fmaf(a[i], b[j], acc[i][j]);
        }
        __syncthreads();
        Ap += 8;
        Bp += (size_t)8 * N;
    }

#pragma unroll
    for (int i = 0; i < 8; i++) {
        int r = rowBase + ((i < 4) ? (ty * 4 + i) : (64 + ty * 4 + (i - 4)));
        float4 c0v = make_float4(acc[i][0], acc[i][1], acc[i][2], acc[i][3]);
        float4 c1v = make_float4(acc[i][4], acc[i][5], acc[i][6], acc[i][7]);
        *(float4*)&Cm[(size_t)r * N + colBase + tx * 4] = c0v;
        *(float4*)&Cm[(size_t)r * N + colBase + 64 + tx * 4] = c1v;
    }
}

// ---------------------------------------------------------------------------
// Fused causal flash attention, fp32.
// One CTA = one (b, h, 64-query tile). 256 threads = 16x16; each thread owns a
// 4x4 tile of S/P and a 4x4 tile of O (rows ty*4.., cols tx*4..). Row softmax
// stats live in registers: each 16-lane half-warp exclusively owns rows
// ty*4..ty*4+3, reductions are shfl-only.
// qkv layout: [B*T, 3C]; head h: q at col h*64, k at C+h*64, v at 2C+h*64.
// ---------------------------------------------------------------------------
__global__ __launch_bounds__(256, 2)
void attn64(const float* __restrict__ qkv, float* __restrict__ att) {
    // Heavy q-tiles (most key tiles) first to reduce wave-tail imbalance.
    const int qt = (int)gridDim.x - 1 - (int)blockIdx.x;
    const int h  = blockIdx.y;
    const int b  = blockIdx.z;
    const int q0 = qt << 6;
    const int tid = threadIdx.x;
    const int tx = tid & 15, ty = tid >> 4;
    const int r0 = ty << 2, c0 = tx << 2;

    __shared__ float Qs[64][64];   // [r][d]   (reads are row-broadcast: pitch 64 OK)
    __shared__ float KP[64][64];   // K^T xor-swizzled: KP[d][c ^ (d&31)]; reused as P[r][c]
    __shared__ float Vs[64][64];   // [c][d]

    const float* base = qkv + (size_t)b * T_ * N3_ + (size_t)h * D_;
    const float* qb = base;
    const float* kb = base + C_;
    const float* vb = base + 2 * C_;

    // Load Q tile [64 x 64]
#pragma unroll
    for (int e = 0; e < 4; e++) {
        int idx4 = e * 256 + tid;          // 0..1023 float4 slots
        int r  = idx4 >> 4;
        int d4 = (idx4 & 15) << 2;
        float4 v = *(const float4*)&qb[(size_t)(q0 + r) * N3_ + d4];
        Qs[r][d4 + 0] = v.x; Qs[r][d4 + 1] = v.y;
        Qs[r][d4 + 2] = v.z; Qs[r][d4 + 3] = v.w;
    }

    float o[4][4];
    float mo[4], lo[4];
#pragma unroll
    for (int i = 0; i < 4; i++) {
        mo[i] = -1e30f;
        lo[i] = 0.f;
#pragma unroll
        for (int j = 0; j < 4; j++) o[i][j] = 0.f;
    }

    const float NEG_INF = __int_as_float(0xff800000u);
    const float scale = 0.125f;  // 1/sqrt(64)

    for (int jt = 0; jt <= qt; jt++) {
        const int k0 = jt << 6;
        // Previous tile's KP(P)/Vs fully consumed; Q store visible (1st iter).
        __syncthreads();

        // Load K (transposed + swizzled) and V tiles.
#pragma unroll
        for (int e = 0; e < 4; e++) {
            int idx4 = e * 256 + tid;
            int c  = idx4 >> 4;
            int d4 = (idx4 & 15) << 2;
            float4 kv = *(const float4*)&kb[(size_t)(k0 + c) * N3_ + d4];
            KP[d4 + 0][c ^ ((d4 + 0) & 31)] = kv.x;
            KP[d4 + 1][c ^ ((d4 + 1) & 31)] = kv.y;
            KP[d4 + 2][c ^ ((d4 + 2) & 31)] = kv.z;
            KP[d4 + 3][c ^ ((d4 + 3) & 31)] = kv.w;
            float4 vv = *(const float4*)&vb[(size_t)(k0 + c) * N3_ + d4];
            *(float4*)&Vs[c][d4] = vv;
        }
        __syncthreads();

        // S = Q @ K^T  (4x4 per thread)
        float s[4][4];
#pragma unroll
        for (int i = 0; i < 4; i++)
#pragma unroll
            for (int j = 0; j < 4; j++) s[i][j] = 0.f;

#pragma unroll 8
        for (int d = 0; d < 64; d++) {
            float a0 = Qs[r0 + 0][d];
            float a1 = Qs[r0 + 1][d];
            float a2 = Qs[r0 + 2][d];
            float a3 = Qs[r0 + 3][d];
            const int m = d & 31;
            float b0 = KP[d][(c0 + 0) ^ m];
            float b1 = KP[d][(c0 + 1) ^ m];
            float b2 = KP[d][(c0 + 2) ^ m];
            float b3 = KP[d][(c0 + 3) ^ m];
            s[0][0] = fmaf(a0, b0, s[0][0]); s[0][1] = fmaf(a0, b1, s[0][1]);
            s[0][2] = fmaf(a0, b2, s[0][2]); s[0][3] = fmaf(a0, b3, s[0][3]);
            s[1][0] = fmaf(a1, b0, s[1][0]); s[1][1] = fmaf(a1, b1, s[1][1]);
            s[1][2] = fmaf(a1, b2, s[1][2]); s[1][3] = fmaf(a1, b3, s[1][3]);
            s[2][0] = fmaf(a2, b0, s[2][0]); s[2][1] = fmaf(a2, b1, s[2][1]);
            s[2][2] = fmaf(a2, b2, s[2][2]); s[2][3] = fmaf(a2, b3, s[2][3]);
            s[3][0] = fmaf(a3, b0, s[3][0]); s[3][1] = fmaf(a3, b1, s[3][1]);
            s[3][2] = fmaf(a3, b2, s[3][2]); s[3][3] = fmaf(a3, b3, s[3][3]);
        }

        // Scale + causal mask (only the diagonal tile needs masking).
        const bool diag = (jt == qt);
        float rm[4];
#pragma unroll
        for (int i = 0; i < 4; i++) {
#pragma unroll
            for (int j = 0; j < 4; j++) {
                float v = s[i][j] * scale;
                if (diag && (c0 + j > r0 + i)) v = NEG_INF;
                s[i][j] = v;
            }
            rm[i] = fmaxf(fmaxf(s[i][0], s[i][1]), fmaxf(s[i][2], s[i][3]));
        }
        // Row-max across the 16 lanes (tx) of this half-warp.
#pragma unroll
        for (int off = 1; off < 16; off <<= 1) {
#pragma unroll
            for (int i = 0; i < 4; i++)
                rm[i] = fmaxf(rm[i], __shfl_xor_sync(0xffffffffu, rm[i], off));
        }

        float sc[4], rs[4];
#pragma unroll
        for (int i = 0; i < 4; i++) {
            float mn = fmaxf(mo[i], rm[i]);
            sc[i] = __expf(mo[i] - mn);
            mo[i] = mn;
            rs[i] = 0.f;
#pragma unroll
            for (int j = 0; j < 4; j++) {
                float p = __expf(s[i][j] - mn);
                s[i][j] = p;
                rs[i] += p;
            }
        }
#pragma unroll
        for (int off = 1; off < 16; off <<= 1) {
#pragma unroll
            for (int i = 0; i < 4; i++)
                rs[i] += __shfl_xor_sync(0xffffffffu, rs[i], off);
        }
#pragma unroll
        for (int i = 0; i < 4; i++) {
            lo[i] = lo[i] * sc[i] + rs[i];
#pragma unroll
            for (int j = 0; j < 4; j++) o[i][j] *= sc[i];
        }

        // All warps must be done reading KP-as-K before overwriting with P.
        __syncthreads();
#pragma unroll
        for (int i = 0; i < 4; i++)
#pragma unroll
            for (int j = 0; j < 4; j++)
                KP[r0 + i][c0 + j] = s[i][j];
        // PV only reads rows r0..r0+3, written entirely by this half-warp.
        __syncwarp();

        // O += P @ V
#pragma unroll 8
        for (int j = 0; j < 64; j++) {
            float p0 = KP[r0 + 0][j];
            float p1 = KP[r0 + 1][j];
            float p2 = KP[r0 + 2][j];
            float p3 = KP[r0 + 3][j];
            float v0 = Vs[j][c0 + 0];
            float v1 = Vs[j][c0 + 1];
            float v2 = Vs[j][c0 + 2];
            float v3 = Vs[j][c0 + 3];
            o[0][0] = fmaf(p0, v0, o[0][0]); o[0][1] = fmaf(p0, v1, o[0][1]);
            o[0][2] = fmaf(p0, v2, o[0][2]); o[0][3] = fmaf(p0, v3, o[0][3]);
            o[1][0] = fmaf(p1, v0, o[1][0]); o[1][1] = fmaf(p1, v1, o[1][1]);
            o[1][2] = fmaf(p1, v2, o[1][2]); o[1][3] = fmaf(p1, v3, o[1][3]);
            o[2][0] = fmaf(p2, v0, o[2][0]); o[2][1] = fmaf(p2, v1, o[2][1]);
            o[2][2] = fmaf(p2, v2, o[2][2]); o[2][3] = fmaf(p2, v3, o[2][3]);
            o[3][0] = fmaf(p3, v0, o[3][0]); o[3][1] = fmaf(p3, v1, o[3][1]);
            o[3][2] = fmaf(p3, v2, o[3][2]); o[3][3] = fmaf(p3, v3, o[3][3]);
        }
    }

    // Epilogue: normalize and write [B,T,C] (head h at columns h*64).
    float* ob = att + ((size_t)(b * T_) + q0) * C_ + (size_t)h * D_;
#pragma unroll
    for (int i = 0; i < 4; i++) {
        float inv = 1.f / lo[i];
        float4 v = make_float4(o[i][0] * inv, o[i][1] * inv,
                               o[i][2] * inv, o[i][3] * inv);
        *(float4*)&ob[(size_t)(r0 + i) * C_ + c0] = v;
    }
}

// ---------------------------------------------------------------------------
// Launch: x @ w_qkv -> g_qkv ; attention -> g_att ; g_att @ w_proj -> out
// ---------------------------------------------------------------------------
extern "C" void kernel_launch(void* const* d_in, const int* in_sizes, int n_in,
                              void* d_out, int out_size) {
    const float* x      = (const float*)d_in[0];
    const float* w_qkv  = (const float*)d_in[1];
    const float* w_proj = (const float*)d_in[2];
    float* out = (float*)d_out;

    void* qkv_p = nullptr;
    void* att_p = nullptr;
    cudaGetSymbolAddress(&qkv_p, g_qkv);
    cudaGetSymbolAddress(&att_p, g_att);
    float* qkv = (float*)qkv_p;
    float* att = (float*)att_p;

    sgemm128<<<dim3(N3_ / 128, M_ / 128), 256>>>(x, w_qkv, qkv, M_, N3_, C_);
    attn64<<<dim3(T_ / 64, H_, B_), 256>>>(qkv, att);
    sgemm128<<<dim3(C_ / 128, M_ / 128), 256>>>(att, w_proj, out, M_, C_, C_);
}

// round 6
// speedup vs baseline: 1.5484x; 1.5484x over previous
#include <cuda_runtime.h>
#include <cstdint>
#include <cstddef>

#define B_  4
#define T_  2048
#define C_  1024
#define H_  16
#define D_  64
#define M_  (B_ * T_)        // 8192
#define N3_ (3 * C_)         // 3072
#define KD_ 1024

// Scratch (static device globals — no allocation in kernel_launch)
__device__ __align__(16) float g_qkv[(size_t)M_ * N3_];     // [B*T, 3C]
__device__ __align__(16) float g_att[(size_t)M_ * C_];      // [B*T, C]
__device__ __align__(16) float g_wqkvT[(size_t)N3_ * KD_];  // w_qkv^T  [N,K]
__device__ __align__(16) float g_wprojT[(size_t)C_ * KD_];  // w_proj^T [N,K]

__device__ __forceinline__ uint32_t f2tf32(float f) {
    uint32_t r;
    asm("cvt.rna.tf32.f32 %0, %1;" : "=r"(r) : "f"(f));
    return r;
}

// mma.sync m16n8k8 tf32 (baseline PTX, maps to HMMA on sm_103)
__device__ __forceinline__ void mma_tf32(float d[4], const uint32_t a[4],
                                         const uint32_t b[2]) {
    asm volatile(
        "mma.sync.aligned.m16n8k8.row.col.f32.tf32.tf32.f32 "
        "{%0,%1,%2,%3}, {%4,%5,%6,%7}, {%8,%9}, {%0,%1,%2,%3};"
        : "+f"(d[0]), "+f"(d[1]), "+f"(d[2]), "+f"(d[3])
        : "r"(a[0]), "r"(a[1]), "r"(a[2]), "r"(a[3]), "r"(b[0]), "r"(b[1]));
}

// ===========================================================================
// TF32 tensor-core GEMM: Cm[M,N] = A[M,1024] @ BT[N,1024]^T
// CTA tile 128x128, BK=16, double-buffered smem (pitch 20: conflict-free for
// the (group, tg) fragment-read pattern). 8 warps, 64x32 warp tile.
// tf32 conversion (cvt.rna) happens once on the LDG->STS path.
// ===========================================================================
#define PITCH 20

__global__ __launch_bounds__(256, 2)
void gemm_mma(const float* __restrict__ A, const float* __restrict__ BT,
              float* __restrict__ Cm, int N) {
    __shared__ float As[2][128][PITCH];
    __shared__ float Bs[2][128][PITCH];

    const int tid = threadIdx.x;
    const int lane = tid & 31, wid = tid >> 5;
    const int g = lane >> 2, tg = lane & 3;
    const int wm = (wid & 1) * 64;       // warp M offset
    const int wn = (wid >> 1) * 32;      // warp N offset
    const int rowBase = blockIdx.y * 128;
    const int colBase = blockIdx.x * 128;

    // Stage-load addressing: 2 float4 rows-halves per operand per thread.
    const int m0 = tid >> 2;             // 0..63
    const int seg = tid & 3;             // 16B segment within BK=16 row
    const float* Ap = A + (size_t)(rowBase + m0) * KD_ + seg * 4;
    const float* Bp = BT + (size_t)(colBase + m0) * KD_ + seg * 4;

    float d[4][4][4];
#pragma unroll
    for (int mt = 0; mt < 4; mt++)
#pragma unroll
        for (int nt = 0; nt < 4; nt++)
#pragma unroll
            for (int q = 0; q < 4; q++) d[mt][nt][q] = 0.f;

    float4 pa0, pa1, pb0, pb1;

#define LDG_STAGE(kt)                                                        \
    do {                                                                     \
        pa0 = *(const float4*)(Ap + (size_t)(kt) * 16);                      \
        pa1 = *(const float4*)(Ap + (size_t)64 * KD_ + (size_t)(kt) * 16);   \
        pb0 = *(const float4*)(Bp + (size_t)(kt) * 16);                      \
        pb1 = *(const float4*)(Bp + (size_t)64 * KD_ + (size_t)(kt) * 16);   \
    } while (0)

#define STS_STAGE(buf)                                                       \
    do {                                                                     \
        float* a0p = &As[buf][m0][seg * 4];                                  \
        float* a1p = &As[buf][m0 + 64][seg * 4];                             \
        float* b0p = &Bs[buf][m0][seg * 4];                                  \
        float* b1p = &Bs[buf][m0 + 64][seg * 4];                             \
        a0p[0] = __uint_as_float(f2tf32(pa0.x));                             \
        a0p[1] = __uint_as_float(f2tf32(pa0.y));                             \
        a0p[2] = __uint_as_float(f2tf32(pa0.z));                             \
        a0p[3] = __uint_as_float(f2tf32(pa0.w));                             \
        a1p[0] = __uint_as_float(f2tf32(pa1.x));                             \
        a1p[1] = __uint_as_float(f2tf32(pa1.y));                             \
        a1p[2] = __uint_as_float(f2tf32(pa1.z));                             \
        a1p[3] = __uint_as_float(f2tf32(pa1.w));                             \
        b0p[0] = __uint_as_float(f2tf32(pb0.x));                             \
        b0p[1] = __uint_as_float(f2tf32(pb0.y));                             \
        b0p[2] = __uint_as_float(f2tf32(pb0.z));                             \
        b0p[3] = __uint_as_float(f2tf32(pb0.w));                             \
        b1p[0] = __uint_as_float(f2tf32(pb1.x));                             \
        b1p[1] = __uint_as_float(f2tf32(pb1.y));                             \
        b1p[2] = __uint_as_float(f2tf32(pb1.z));                             \
        b1p[3] = __uint_as_float(f2tf32(pb1.w));                             \
    } while (0)

    LDG_STAGE(0);
    STS_STAGE(0);

    const int NSTAGE = KD_ / 16;   // 64
    for (int kt = 0; kt < NSTAGE; kt++) {
        __syncthreads();           // stage kt stores visible; prior reads done
        const int buf = kt & 1;
        if (kt + 1 < NSTAGE) LDG_STAGE(kt + 1);

#pragma unroll
        for (int kk = 0; kk < 16; kk += 8) {
            uint32_t af[4][4], bf[4][2];
#pragma unroll
            for (int mt = 0; mt < 4; mt++) {
                const int r = wm + mt * 16 + g;
                af[mt][0] = __float_as_uint(As[buf][r][kk + tg]);
                af[mt][1] = __float_as_uint(As[buf][r + 8][kk + tg]);
                af[mt][2] = __float_as_uint(As[buf][r][kk + tg + 4]);
                af[mt][3] = __float_as_uint(As[buf][r + 8][kk + tg + 4]);
            }
#pragma unroll
            for (int nt = 0; nt < 4; nt++) {
                const int c = wn + nt * 8 + g;
                bf[nt][0] = __float_as_uint(Bs[buf][c][kk + tg]);
                bf[nt][1] = __float_as_uint(Bs[buf][c][kk + tg + 4]);
            }
#pragma unroll
            for (int mt = 0; mt < 4; mt++)
#pragma unroll
                for (int nt = 0; nt < 4; nt++)
                    mma_tf32(d[mt][nt], af[mt], bf[nt]);
        }

        if (kt + 1 < NSTAGE) {
            __syncthreads();       // all warps done reading buf^1 (at kt-1)
            STS_STAGE(buf ^ 1);
        }
    }

    // Epilogue: c0/c1 -> (row g, cols 2tg,2tg+1); c2/c3 -> row g+8.
#pragma unroll
    for (int mt = 0; mt < 4; mt++) {
        const int r = rowBase + wm + mt * 16 + g;
#pragma unroll
        for (int nt = 0; nt < 4; nt++) {
            const int c = colBase + wn + nt * 8 + 2 * tg;
            float* p = Cm + (size_t)r * N + c;
            *(float2*)p = make_float2(d[mt][nt][0], d[mt][nt][1]);
            *(float2*)(p + (size_t)8 * N) = make_float2(d[mt][nt][2], d[mt][nt][3]);
        }
    }
#undef LDG_STAGE
#undef STS_STAGE
}

// ===========================================================================
// Transpose: out[c][r] = in[r][c]   (in: [R, Cc] row-major)
// ===========================================================================
__global__ void transposeK(const float* __restrict__ in, float* __restrict__ out,
                           int R, int Cc) {
    __shared__ float t[32][33];
    const int c0 = blockIdx.x * 32, r0 = blockIdx.y * 32;
    const int tx = threadIdx.x, ty = threadIdx.y;
#pragma unroll
    for (int i = 0; i < 32; i += 8)
        t[ty + i][tx] = in[(size_t)(r0 + ty + i) * Cc + c0 + tx];
    __syncthreads();
#pragma unroll
    for (int i = 0; i < 32; i += 8)
        out[(size_t)(c0 + ty + i) * R + r0 + tx] = t[tx][ty + i];
}

// ===========================================================================
// Fused causal flash attention, fp32 (unchanged from passing round).
// ===========================================================================
__global__ __launch_bounds__(256, 2)
void attn64(const float* __restrict__ qkv, float* __restrict__ att) {
    const int qt = (int)gridDim.x - 1 - (int)blockIdx.x;
    const int h  = blockIdx.y;
    const int b  = blockIdx.z;
    const int q0 = qt << 6;
    const int tid = threadIdx.x;
    const int tx = tid & 15, ty = tid >> 4;
    const int r0 = ty << 2, c0 = tx << 2;

    __shared__ float Qs[64][64];
    __shared__ float KP[64][64];
    __shared__ float Vs[64][64];

    const float* base = qkv + (size_t)b * T_ * N3_ + (size_t)h * D_;
    const float* qb = base;
    const float* kb = base + C_;
    const float* vb = base + 2 * C_;

#pragma unroll
    for (int e = 0; e < 4; e++) {
        int idx4 = e * 256 + tid;
        int r  = idx4 >> 4;
        int d4 = (idx4 & 15) << 2;
        float4 v = *(const float4*)&qb[(size_t)(q0 + r) * N3_ + d4];
        Qs[r][d4 + 0] = v.x; Qs[r][d4 + 1] = v.y;
        Qs[r][d4 + 2] = v.z; Qs[r][d4 + 3] = v.w;
    }

    float o[4][4];
    float mo[4], lo[4];
#pragma unroll
    for (int i = 0; i < 4; i++) {
        mo[i] = -1e30f;
        lo[i] = 0.f;
#pragma unroll
        for (int j = 0; j < 4; j++) o[i][j] = 0.f;
    }

    const float NEG_INF = __int_as_float(0xff800000u);
    const float scale = 0.125f;

    for (int jt = 0; jt <= qt; jt++) {
        const int k0 = jt << 6;
        __syncthreads();

#pragma unroll
        for (int e = 0; e < 4; e++) {
            int idx4 = e * 256 + tid;
            int c  = idx4 >> 4;
            int d4 = (idx4 & 15) << 2;
            float4 kv = *(const float4*)&kb[(size_t)(k0 + c) * N3_ + d4];
            KP[d4 + 0][c ^ ((d4 + 0) & 31)] = kv.x;
            KP[d4 + 1][c ^ ((d4 + 1) & 31)] = kv.y;
            KP[d4 + 2][c ^ ((d4 + 2) & 31)] = kv.z;
            KP[d4 + 3][c ^ ((d4 + 3) & 31)] = kv.w;
            float4 vv = *(const float4*)&vb[(size_t)(k0 + c) * N3_ + d4];
            *(float4*)&Vs[c][d4] = vv;
        }
        __syncthreads();

        float s[4][4];
#pragma unroll
        for (int i = 0; i < 4; i++)
#pragma unroll
            for (int j = 0; j < 4; j++) s[i][j] = 0.f;

#pragma unroll 8
        for (int d = 0; d < 64; d++) {
            float a0 = Qs[r0 + 0][d];
            float a1 = Qs[r0 + 1][d];
            float a2 = Qs[r0 + 2][d];
            float a3 = Qs[r0 + 3][d];
            const int m = d & 31;
            float b0 = KP[d][(c0 + 0) ^ m];
            float b1 = KP[d][(c0 + 1) ^ m];
            float b2 = KP[d][(c0 + 2) ^ m];
            float b3 = KP[d][(c0 + 3) ^ m];
            s[0][0] = fmaf(a0, b0, s[0][0]); s[0][1] = fmaf(a0, b1, s[0][1]);
            s[0][2] = fmaf(a0, b2, s[0][2]); s[0][3] = fmaf(a0, b3, s[0][3]);
            s[1][0] = fmaf(a1, b0, s[1][0]); s[1][1] = fmaf(a1, b1, s[1][1]);
            s[1][2] = fmaf(a1, b2, s[1][2]); s[1][3] = fmaf(a1, b3, s[1][3]);
            s[2][0] = fmaf(a2, b0, s[2][0]); s[2][1] = fmaf(a2, b1, s[2][1]);
            s[2][2] = fmaf(a2, b2, s[2][2]); s[2][3] = fmaf(a2, b3, s[2][3]);
            s[3][0] = fmaf(a3, b0, s[3][0]); s[3][1] = fmaf(a3, b1, s[3][1]);
            s[3][2] = fmaf(a3, b2, s[3][2]); s[3][3] = fmaf(a3, b3, s[3][3]);
        }

        const bool diag = (jt == qt);
        float rm[4];
#pragma unroll
        for (int i = 0; i < 4; i++) {
#pragma unroll
            for (int j = 0; j < 4; j++) {
                float v = s[i][j] * scale;
                if (diag && (c0 + j > r0 + i)) v = NEG_INF;
                s[i][j] = v;
            }
            rm[i] = fmaxf(fmaxf(s[i][0], s[i][1]), fmaxf(s[i][2], s[i][3]));
        }
#pragma unroll
        for (int off = 1; off < 16; off <<= 1) {
#pragma unroll
            for (int i = 0; i < 4; i++)
                rm[i] = fmaxf(rm[i], __shfl_xor_sync(0xffffffffu, rm[i], off));
        }

        float sc[4], rs[4];
#pragma unroll
        for (int i = 0; i < 4; i++) {
            float mn = fmaxf(mo[i], rm[i]);
            sc[i] = __expf(mo[i] - mn);
            mo[i] = mn;
            rs[i] = 0.f;
#pragma unroll
            for (int j = 0; j < 4; j++) {
                float p = __expf(s[i][j] - mn);
                s[i][j] = p;
                rs[i] += p;
            }
        }
#pragma unroll
        for (int off = 1; off < 16; off <<= 1) {
#pragma unroll
            for (int i = 0; i < 4; i++)
                rs[i] += __shfl_xor_sync(0xffffffffu, rs[i], off);
        }
#pragma unroll
        for (int i = 0; i < 4; i++) {
            lo[i] = lo[i] * sc[i] + rs[i];
#pragma unroll
            for (int j = 0; j < 4; j++) o[i][j] *= sc[i];
        }

        __syncthreads();
#pragma unroll
        for (int i = 0; i < 4; i++)
#pragma unroll
            for (int j = 0; j < 4; j++)
                KP[r0 + i][c0 + j] = s[i][j];
        __syncwarp();

#pragma unroll 8
        for (int j = 0; j < 64; j++) {
            float p0 = KP[r0 + 0][j];
            float p1 = KP[r0 + 1][j];
            float p2 = KP[r0 + 2][j];
            float p3 = KP[r0 + 3][j];
            float v0 = Vs[j][c0 + 0];
            float v1 = Vs[j][c0 + 1];
            float v2 = Vs[j][c0 + 2];
            float v3 = Vs[j][c0 + 3];
            o[0][0] = fmaf(p0, v0, o[0][0]); o[0][1] = fmaf(p0, v1, o[0][1]);
            o[0][2] = fmaf(p0, v2, o[0][2]); o[0][3] = fmaf(p0, v3, o[0][3]);
            o[1][0] = fmaf(p1, v0, o[1][0]); o[1][1] = fmaf(p1, v1, o[1][1]);
            o[1][2] = fmaf(p1, v2, o[1][2]); o[1][3] = fmaf(p1, v3, o[1][3]);
            o[2][0] = fmaf(p2, v0, o[2][0]); o[2][1] = fmaf(p2, v1, o[2][1]);
            o[2][2] = fmaf(p2, v2, o[2][2]); o[2][3] = fmaf(p2, v3, o[2][3]);
            o[3][0] = fmaf(p3, v0, o[3][0]); o[3][1] = fmaf(p3, v1, o[3][1]);
            o[3][2] = fmaf(p3, v2, o[3][2]); o[3][3] = fmaf(p3, v3, o[3][3]);
        }
    }

    float* ob = att + ((size_t)(b * T_) + q0) * C_ + (size_t)h * D_;
#pragma unroll
    for (int i = 0; i < 4; i++) {
        float inv = 1.f / lo[i];
        float4 v = make_float4(o[i][0] * inv, o[i][1] * inv,
                               o[i][2] * inv, o[i][3] * inv);
        *(float4*)&ob[(size_t)(r0 + i) * C_ + c0] = v;
    }
}

// ===========================================================================
// Launch
// ===========================================================================
extern "C" void kernel_launch(void* const* d_in, const int* in_sizes, int n_in,
                              void* d_out, int out_size) {
    const float* x      = (const float*)d_in[0];
    const float* w_qkv  = (const float*)d_in[1];
    const float* w_proj = (const float*)d_in[2];
    float* out = (float*)d_out;

    void *qkv_p, *att_p, *wqkvT_p, *wprojT_p;
    cudaGetSymbolAddress(&qkv_p, g_qkv);
    cudaGetSymbolAddress(&att_p, g_att);
    cudaGetSymbolAddress(&wqkvT_p, g_wqkvT);
    cudaGetSymbolAddress(&wprojT_p, g_wprojT);
    float* qkv    = (float*)qkv_p;
    float* att    = (float*)att_p;
    float* wqkvT  = (float*)wqkvT_p;
    float* wprojT = (float*)wprojT_p;

    transposeK<<<dim3(N3_ / 32, KD_ / 32), dim3(32, 8)>>>(w_qkv, wqkvT, KD_, N3_);
    transposeK<<<dim3(C_ / 32, KD_ / 32), dim3(32, 8)>>>(w_proj, wprojT, KD_, C_);

    gemm_mma<<<dim3(N3_ / 128, M_ / 128), 256>>>(x, wqkvT, qkv, N3_);
    attn64<<<dim3(T_ / 64, H_, B_), 256>>>(qkv, att);
    gemm_mma<<<dim3(C_ / 128, M_ / 128), 256>>>(att, wprojT, out, C_);
}

// round 9
// speedup vs baseline: 3.0057x; 1.9412x over previous
#include <cuda_runtime.h>
#include <cstdint>
#include <cstddef>

#define B_  4
#define T_  2048
#define C_  1024
#define H_  16
#define D_  64
#define M_  (B_ * T_)        // 8192
#define N3_ (3 * C_)         // 3072
#define KD_ 1024

// Scratch (static device globals — no allocation in kernel_launch)
__device__ __align__(16) float g_qkv[(size_t)M_ * N3_];     // [B*T, 3C]
__device__ __align__(16) float g_att[(size_t)M_ * C_];      // [B*T, C]
__device__ __align__(16) float g_wqkvT[(size_t)N3_ * KD_];  // w_qkv^T  [N,K]
__device__ __align__(16) float g_wprojT[(size_t)C_ * KD_];  // w_proj^T [N,K]

__device__ __forceinline__ uint32_t f2tf32(float f) {
    uint32_t r;
    asm("cvt.rna.tf32.f32 %0, %1;" : "=r"(r) : "f"(f));
    return r;
}
__device__ __forceinline__ float tf32f(float f) {
    return __uint_as_float(f2tf32(f));
}

// mma.sync m16n8k8 tf32 (baseline PTX, maps to HMMA on sm_103)
__device__ __forceinline__ void mma_tf32(float d[4], const uint32_t a[4],
                                         const uint32_t b[2]) {
    asm volatile(
        "mma.sync.aligned.m16n8k8.row.col.f32.tf32.tf32.f32 "
        "{%0,%1,%2,%3}, {%4,%5,%6,%7}, {%8,%9}, {%0,%1,%2,%3};"
        : "+f"(d[0]), "+f"(d[1]), "+f"(d[2]), "+f"(d[3])
        : "r"(a[0]), "r"(a[1]), "r"(a[2]), "r"(a[3]), "r"(b[0]), "r"(b[1]));
}

// ===========================================================================
// TF32 tensor-core GEMM: Cm[M,N] = A[M,1024] @ BT[N,1024]^T  (unchanged)
// ===========================================================================
#define PITCH 20

__global__ __launch_bounds__(256, 2)
void gemm_mma(const float* __restrict__ A, const float* __restrict__ BT,
              float* __restrict__ Cm, int N) {
    __shared__ float As[2][128][PITCH];
    __shared__ float Bs[2][128][PITCH];

    const int tid = threadIdx.x;
    const int lane = tid & 31, wid = tid >> 5;
    const int g = lane >> 2, tg = lane & 3;
    const int wm = (wid & 1) * 64;
    const int wn = (wid >> 1) * 32;
    const int rowBase = blockIdx.y * 128;
    const int colBase = blockIdx.x * 128;

    const int m0 = tid >> 2;
    const int seg = tid & 3;
    const float* Ap = A + (size_t)(rowBase + m0) * KD_ + seg * 4;
    const float* Bp = BT + (size_t)(colBase + m0) * KD_ + seg * 4;

    float d[4][4][4];
#pragma unroll
    for (int mt = 0; mt < 4; mt++)
#pragma unroll
        for (int nt = 0; nt < 4; nt++)
#pragma unroll
            for (int q = 0; q < 4; q++) d[mt][nt][q] = 0.f;

    float4 pa0, pa1, pb0, pb1;

#define LDG_STAGE(kt)                                                        \
    do {                                                                     \
        pa0 = *(const float4*)(Ap + (size_t)(kt) * 16);                      \
        pa1 = *(const float4*)(Ap + (size_t)64 * KD_ + (size_t)(kt) * 16);   \
        pb0 = *(const float4*)(Bp + (size_t)(kt) * 16);                      \
        pb1 = *(const float4*)(Bp + (size_t)64 * KD_ + (size_t)(kt) * 16);   \
    } while (0)

#define STS_STAGE(buf)                                                       \
    do {                                                                     \
        float* a0p = &As[buf][m0][seg * 4];                                  \
        float* a1p = &As[buf][m0 + 64][seg * 4];                             \
        float* b0p = &Bs[buf][m0][seg * 4];                                  \
        float* b1p = &Bs[buf][m0 + 64][seg * 4];                             \
        a0p[0] = tf32f(pa0.x); a0p[1] = tf32f(pa0.y);                        \
        a0p[2] = tf32f(pa0.z); a0p[3] = tf32f(pa0.w);                        \
        a1p[0] = tf32f(pa1.x); a1p[1] = tf32f(pa1.y);                        \
        a1p[2] = tf32f(pa1.z); a1p[3] = tf32f(pa1.w);                        \
        b0p[0] = tf32f(pb0.x); b0p[1] = tf32f(pb0.y);                        \
        b0p[2] = tf32f(pb0.z); b0p[3] = tf32f(pb0.w);                        \
        b1p[0] = tf32f(pb1.x); b1p[1] = tf32f(pb1.y);                        \
        b1p[2] = tf32f(pb1.z); b1p[3] = tf32f(pb1.w);                        \
    } while (0)

    LDG_STAGE(0);
    STS_STAGE(0);

    const int NSTAGE = KD_ / 16;   // 64
    for (int kt = 0; kt < NSTAGE; kt++) {
        __syncthreads();
        const int buf = kt & 1;
        if (kt + 1 < NSTAGE) LDG_STAGE(kt + 1);

#pragma unroll
        for (int kk = 0; kk < 16; kk += 8) {
            uint32_t af[4][4], bf[4][2];
#pragma unroll
            for (int mt = 0; mt < 4; mt++) {
                const int r = wm + mt * 16 + g;
                af[mt][0] = __float_as_uint(As[buf][r][kk + tg]);
                af[mt][1] = __float_as_uint(As[buf][r + 8][kk + tg]);
                af[mt][2] = __float_as_uint(As[buf][r][kk + tg + 4]);
                af[mt][3] = __float_as_uint(As[buf][r + 8][kk + tg + 4]);
            }
#pragma unroll
            for (int nt = 0; nt < 4; nt++) {
                const int c = wn + nt * 8 + g;
                bf[nt][0] = __float_as_uint(Bs[buf][c][kk + tg]);
                bf[nt][1] = __float_as_uint(Bs[buf][c][kk + tg + 4]);
            }
#pragma unroll
            for (int mt = 0; mt < 4; mt++)
#pragma unroll
                for (int nt = 0; nt < 4; nt++)
                    mma_tf32(d[mt][nt], af[mt], bf[nt]);
        }

        if (kt + 1 < NSTAGE) {
            __syncthreads();
            STS_STAGE(buf ^ 1);
        }
    }

#pragma unroll
    for (int mt = 0; mt < 4; mt++) {
        const int r = rowBase + wm + mt * 16 + g;
#pragma unroll
        for (int nt = 0; nt < 4; nt++) {
            const int c = colBase + wn + nt * 8 + 2 * tg;
            float* p = Cm + (size_t)r * N + c;
            *(float2*)p = make_float2(d[mt][nt][0], d[mt][nt][1]);
            *(float2*)(p + (size_t)8 * N) = make_float2(d[mt][nt][2], d[mt][nt][3]);
        }
    }
#undef LDG_STAGE
#undef STS_STAGE
}

// ===========================================================================
// Transpose: out[c][r] = in[r][c]
// ===========================================================================
__global__ void transposeK(const float* __restrict__ in, float* __restrict__ out,
                           int R, int Cc) {
    __shared__ float t[32][33];
    const int c0 = blockIdx.x * 32, r0 = blockIdx.y * 32;
    const int tx = threadIdx.x, ty = threadIdx.y;
#pragma unroll
    for (int i = 0; i < 32; i += 8)
        t[ty + i][tx] = in[(size_t)(r0 + ty + i) * Cc + c0 + tx];
    __syncthreads();
#pragma unroll
    for (int i = 0; i < 32; i += 8)
        out[(size_t)(c0 + ty + i) * R + r0 + tx] = t[tx][ty + i];
}

// ===========================================================================
// Tensor-core causal flash attention (tf32 mma).
// CTA = 128 queries x (b,h). 8 warps, 16 q-rows each (warp-private rows).
// KV tile = 64. S accumulators hold softmax in the mma C-layout; P goes
// through a warp-private smem tile (syncwarp only) and feeds PV as A-frags.
// Pitches: Q/K/P = 68 floats ((4g+tg)%32 unique), V = 72 ((8tg+g)%32 unique).
// ===========================================================================
#define QTILE 128
#define KTILE 64
#define QP 68
#define KPCH 68
#define VP 72
#define PP 68
#define ATT_SMEM ((QTILE * QP + KTILE * KPCH + KTILE * VP + QTILE * PP) * 4)

__global__ __launch_bounds__(256, 2)
void attn_mma(const float* __restrict__ qkv, float* __restrict__ att) {
    extern __shared__ float sm[];
    float* Qs = sm;                       // [128][68]
    float* Ks = Qs + QTILE * QP;          // [64][68]
    float* Vs = Ks + KTILE * KPCH;        // [64][72]
    float* Ps = Vs + KTILE * VP;          // [128][68]

    const int qt = (int)gridDim.x - 1 - (int)blockIdx.x;  // heavy tiles first
    const int h = blockIdx.y, b = blockIdx.z;
    const int q0 = qt * QTILE;
    const int tid = threadIdx.x;
    const int lane = tid & 31, w = tid >> 5;
    const int g = lane >> 2, tg = lane & 3;

    const float* base = qkv + (size_t)b * T_ * N3_ + (size_t)h * D_;
    const float* qb = base;
    const float* kb = base + C_;
    const float* vb = base + 2 * C_;

    // Load Q tile [128 x 64] as tf32 (8 float4 per thread)
#pragma unroll
    for (int e = 0; e < 8; e++) {
        int i4 = e * 256 + tid;
        int r = i4 >> 4, d4 = (i4 & 15) << 2;
        float4 v = *(const float4*)&qb[(size_t)(q0 + r) * N3_ + d4];
        float* p = &Qs[r * QP + d4];
        p[0] = tf32f(v.x); p[1] = tf32f(v.y);
        p[2] = tf32f(v.z); p[3] = tf32f(v.w);
    }

    float o[8][4];
#pragma unroll
    for (int nt = 0; nt < 8; nt++)
#pragma unroll
        for (int q = 0; q < 4; q++) o[nt][q] = 0.f;
    float m0 = -1e30f, m1 = -1e30f, l0 = 0.f, l1 = 0.f;

    const int rowA = 16 * w + g;       // q-row of c0/c1
    const int rowB = rowA + 8;         // q-row of c2/c3
    const float scale = 0.125f;
    const int ntiles = 2 * qt + 2;

    for (int jt = 0; jt < ntiles; jt++) {
        const int k0 = jt * KTILE;
        __syncthreads();   // prior iter's K/V reads done (and Q stores visible)

        // Load K, V tiles [64 x 64] (4 float4 each per thread)
#pragma unroll
        for (int e = 0; e < 4; e++) {
            int i4 = e * 256 + tid;
            int r = i4 >> 4, d4 = (i4 & 15) << 2;
            float4 kv = *(const float4*)&kb[(size_t)(k0 + r) * N3_ + d4];
            float* kp = &Ks[r * KPCH + d4];
            kp[0] = tf32f(kv.x); kp[1] = tf32f(kv.y);
            kp[2] = tf32f(kv.z); kp[3] = tf32f(kv.w);
            float4 vv = *(const float4*)&vb[(size_t)(k0 + r) * N3_ + d4];
            float* vp = &Vs[r * VP + d4];
            vp[0] = tf32f(vv.x); vp[1] = tf32f(vv.y);
            vp[2] = tf32f(vv.z); vp[3] = tf32f(vv.w);
        }
        __syncthreads();

        // ---- S = Q @ K^T (16 x 64 per warp) ----
        float s[8][4];
#pragma unroll
        for (int nt = 0; nt < 8; nt++)
#pragma unroll
            for (int q = 0; q < 4; q++) s[nt][q] = 0.f;

#pragma unroll
        for (int kk = 0; kk < 8; kk++) {
            uint32_t a[4];
            a[0] = __float_as_uint(Qs[rowA * QP + 8 * kk + tg]);
            a[1] = __float_as_uint(Qs[rowB * QP + 8 * kk + tg]);
            a[2] = __float_as_uint(Qs[rowA * QP + 8 * kk + tg + 4]);
            a[3] = __float_as_uint(Qs[rowB * QP + 8 * kk + tg + 4]);
#pragma unroll
            for (int nt = 0; nt < 8; nt++) {
                uint32_t bb[2];
                bb[0] = __float_as_uint(Ks[(8 * nt + g) * KPCH + 8 * kk + tg]);
                bb[1] = __float_as_uint(Ks[(8 * nt + g) * KPCH + 8 * kk + tg + 4]);
                mma_tf32(s[nt], a, bb);
            }
        }

        // ---- softmax (register-resident, quad reductions) ----
        const bool masked = (jt >= 2 * qt);
        const int qr0 = q0 + rowA, qr1 = q0 + rowB;
        float rm0 = -1e30f, rm1 = -1e30f;
#pragma unroll
        for (int nt = 0; nt < 8; nt++) {
            const int key = k0 + 8 * nt + 2 * tg;
            s[nt][0] *= scale; s[nt][1] *= scale;
            s[nt][2] *= scale; s[nt][3] *= scale;
            if (masked) {
                if (key     > qr0) s[nt][0] = -1e30f;
                if (key + 1 > qr0) s[nt][1] = -1e30f;
                if (key     > qr1) s[nt][2] = -1e30f;
                if (key + 1 > qr1) s[nt][3] = -1e30f;
            }
            rm0 = fmaxf(rm0, fmaxf(s[nt][0], s[nt][1]));
            rm1 = fmaxf(rm1, fmaxf(s[nt][2], s[nt][3]));
        }
#pragma unroll
        for (int off = 1; off < 4; off <<= 1) {
            rm0 = fmaxf(rm0, __shfl_xor_sync(0xffffffffu, rm0, off));
            rm1 = fmaxf(rm1, __shfl_xor_sync(0xffffffffu, rm1, off));
        }
        const float mn0 = fmaxf(m0, rm0), mn1 = fmaxf(m1, rm1);
        const float al0 = __expf(m0 - mn0), al1 = __expf(m1 - mn1);
        m0 = mn0; m1 = mn1;

        float sum0 = 0.f, sum1 = 0.f;
#pragma unroll
        for (int nt = 0; nt < 8; nt++) {
            s[nt][0] = __expf(s[nt][0] - mn0); sum0 += s[nt][0];
            s[nt][1] = __expf(s[nt][1] - mn0); sum0 += s[nt][1];
            s[nt][2] = __expf(s[nt][2] - mn1); sum1 += s[nt][2];
            s[nt][3] = __expf(s[nt][3] - mn1); sum1 += s[nt][3];
        }
#pragma unroll
        for (int off = 1; off < 4; off <<= 1) {
            sum0 += __shfl_xor_sync(0xffffffffu, sum0, off);
            sum1 += __shfl_xor_sync(0xffffffffu, sum1, off);
        }
        l0 = l0 * al0 + sum0;
        l1 = l1 * al1 + sum1;
#pragma unroll
        for (int nt = 0; nt < 8; nt++) {
            o[nt][0] *= al0; o[nt][1] *= al0;
            o[nt][2] *= al1; o[nt][3] *= al1;
        }

        // ---- P -> warp-private smem (tf32), then O += P @ V ----
#pragma unroll
        for (int nt = 0; nt < 8; nt++) {
            *(float2*)&Ps[rowA * PP + 8 * nt + 2 * tg] =
                make_float2(tf32f(s[nt][0]), tf32f(s[nt][1]));
            *(float2*)&Ps[rowB * PP + 8 * nt + 2 * tg] =
                make_float2(tf32f(s[nt][2]), tf32f(s[nt][3]));
        }
        __syncwarp();

#pragma unroll
        for (int kk = 0; kk < 8; kk++) {
            uint32_t a[4];
            a[0] = __float_as_uint(Ps[rowA * PP + 8 * kk + tg]);
            a[1] = __float_as_uint(Ps[rowB * PP + 8 * kk + tg]);
            a[2] = __float_as_uint(Ps[rowA * PP + 8 * kk + tg + 4]);
            a[3] = __float_as_uint(Ps[rowB * PP + 8 * kk + tg + 4]);
#pragma unroll
            for (int nt = 0; nt < 8; nt++) {
                uint32_t bb[2];
                bb[0] = __float_as_uint(Vs[(8 * kk + tg) * VP + 8 * nt + g]);
                bb[1] = __float_as_uint(Vs[(8 * kk + tg + 4) * VP + 8 * nt + g]);
                mma_tf32(o[nt], a, bb);
            }
        }
    }

    // Epilogue: normalize and store [B,T,C], head h at cols h*64.
    const float inv0 = 1.f / l0, inv1 = 1.f / l1;
    float* obA = att + ((size_t)(b * T_) + q0 + rowA) * C_ + (size_t)h * D_;
    float* obB = att + ((size_t)(b * T_) + q0 + rowB) * C_ + (size_t)h * D_;
#pragma unroll
    for (int nt = 0; nt < 8; nt++) {
        const int c = 8 * nt + 2 * tg;
        *(float2*)(obA + c) = make_float2(o[nt][0] * inv0, o[nt][1] * inv0);
        *(float2*)(obB + c) = make_float2(o[nt][2] * inv1, o[nt][3] * inv1);
    }
}

// ===========================================================================
// Launch
// ===========================================================================
extern "C" void kernel_launch(void* const* d_in, const int* in_sizes, int n_in,
                              void* d_out, int out_size) {
    const float* x      = (const float*)d_in[0];
    const float* w_qkv  = (const float*)d_in[1];
    const float* w_proj = (const float*)d_in[2];
    float* out = (float*)d_out;

    void *qkv_p, *att_p, *wqkvT_p, *wprojT_p;
    cudaGetSymbolAddress(&qkv_p, g_qkv);
    cudaGetSymbolAddress(&att_p, g_att);
    cudaGetSymbolAddress(&wqkvT_p, g_wqkvT);
    cudaGetSymbolAddress(&wprojT_p, g_wprojT);
    float* qkv    = (float*)qkv_p;
    float* att    = (float*)att_p;
    float* wqkvT  = (float*)wqkvT_p;
    float* wprojT = (float*)wprojT_p;

    cudaFuncSetAttribute(attn_mma, cudaFuncAttributeMaxDynamicSharedMemorySize,
                         ATT_SMEM);

    transposeK<<<dim3(N3_ / 32, KD_ / 32), dim3(32, 8)>>>(w_qkv, wqkvT, KD_, N3_);
    transposeK<<<dim3(C_ / 32, KD_ / 32), dim3(32, 8)>>>(w_proj, wprojT, KD_, C_);

    gemm_mma<<<dim3(N3_ / 128, M_ / 128), 256>>>(x, wqkvT, qkv, N3_);
    attn_mma<<<dim3(T_ / QTILE, H_, B_), 256, ATT_SMEM>>>(qkv, att);
    gemm_mma<<<dim3(C_ / 128, M_ / 128), 256>>>(att, wprojT, out, C_);
}

// round 10
// speedup vs baseline: 3.3494x; 1.1143x over previous
#include <cuda_runtime.h>
#include <cuda_fp16.h>
#include <cstdint>
#include <cstddef>

#define B_  4
#define T_  2048
#define C_  1024
#define H_  16
#define D_  64
#define M_  (B_ * T_)        // 8192
#define N3_ (3 * C_)         // 3072
#define KD_ 1024

// Scratch (static device globals — no allocation in kernel_launch)
__device__ __align__(16) float g_qkv[(size_t)M_ * N3_];     // [B*T, 3C]
__device__ __align__(16) float g_att[(size_t)M_ * C_];      // [B*T, C]
__device__ __align__(16) float g_wqkvT[(size_t)N3_ * KD_];  // w_qkv^T  [N,K]
__device__ __align__(16) float g_wprojT[(size_t)C_ * KD_];  // w_proj^T [N,K]

__device__ __forceinline__ uint32_t f2tf32(float f) {
    uint32_t r;
    asm("cvt.rna.tf32.f32 %0, %1;" : "=r"(r) : "f"(f));
    return r;
}
__device__ __forceinline__ float tf32f(float f) {
    return __uint_as_float(f2tf32(f));
}

// mma.sync m16n8k8 tf32 (baseline PTX, maps to HMMA on sm_103)
__device__ __forceinline__ void mma_tf32(float d[4], const uint32_t a[4],
                                         const uint32_t b[2]) {
    asm volatile(
        "mma.sync.aligned.m16n8k8.row.col.f32.tf32.tf32.f32 "
        "{%0,%1,%2,%3}, {%4,%5,%6,%7}, {%8,%9}, {%0,%1,%2,%3};"
        : "+f"(d[0]), "+f"(d[1]), "+f"(d[2]), "+f"(d[3])
        : "r"(a[0]), "r"(a[1]), "r"(a[2]), "r"(a[3]), "r"(b[0]), "r"(b[1]));
}

// mma.sync m16n8k16 fp16 with fp32 accumulate
__device__ __forceinline__ void mma_f16(float d[4], const uint32_t a[4],
                                        const uint32_t b[2]) {
    asm volatile(
        "mma.sync.aligned.m16n8k16.row.col.f32.f16.f16.f32 "
        "{%0,%1,%2,%3}, {%4,%5,%6,%7}, {%8,%9}, {%0,%1,%2,%3};"
        : "+f"(d[0]), "+f"(d[1]), "+f"(d[2]), "+f"(d[3])
        : "r"(a[0]), "r"(a[1]), "r"(a[2]), "r"(a[3]), "r"(b[0]), "r"(b[1]));
}

// ===========================================================================
// TF32 tensor-core GEMM: Cm[M,N] = A[M,1024] @ BT[N,1024]^T  (unchanged)
// ===========================================================================
#define PITCH 20

__global__ __launch_bounds__(256, 2)
void gemm_mma(const float* __restrict__ A, const float* __restrict__ BT,
              float* __restrict__ Cm, int N) {
    __shared__ float As[2][128][PITCH];
    __shared__ float Bs[2][128][PITCH];

    const int tid = threadIdx.x;
    const int lane = tid & 31, wid = tid >> 5;
    const int g = lane >> 2, tg = lane & 3;
    const int wm = (wid & 1) * 64;
    const int wn = (wid >> 1) * 32;
    const int rowBase = blockIdx.y * 128;
    const int colBase = blockIdx.x * 128;

    const int m0 = tid >> 2;
    const int seg = tid & 3;
    const float* Ap = A + (size_t)(rowBase + m0) * KD_ + seg * 4;
    const float* Bp = BT + (size_t)(colBase + m0) * KD_ + seg * 4;

    float d[4][4][4];
#pragma unroll
    for (int mt = 0; mt < 4; mt++)
#pragma unroll
        for (int nt = 0; nt < 4; nt++)
#pragma unroll
            for (int q = 0; q < 4; q++) d[mt][nt][q] = 0.f;

    float4 pa0, pa1, pb0, pb1;

#define LDG_STAGE(kt)                                                        \
    do {                                                                     \
        pa0 = *(const float4*)(Ap + (size_t)(kt) * 16);                      \
        pa1 = *(const float4*)(Ap + (size_t)64 * KD_ + (size_t)(kt) * 16);   \
        pb0 = *(const float4*)(Bp + (size_t)(kt) * 16);                      \
        pb1 = *(const float4*)(Bp + (size_t)64 * KD_ + (size_t)(kt) * 16);   \
    } while (0)

#define STS_STAGE(buf)                                                       \
    do {                                                                     \
        float* a0p = &As[buf][m0][seg * 4];                                  \
        float* a1p = &As[buf][m0 + 64][seg * 4];                             \
        float* b0p = &Bs[buf][m0][seg * 4];                                  \
        float* b1p = &Bs[buf][m0 + 64][seg * 4];                             \
        a0p[0] = tf32f(pa0.x); a0p[1] = tf32f(pa0.y);                        \
        a0p[2] = tf32f(pa0.z); a0p[3] = tf32f(pa0.w);                        \
        a1p[0] = tf32f(pa1.x); a1p[1] = tf32f(pa1.y);                        \
        a1p[2] = tf32f(pa1.z); a1p[3] = tf32f(pa1.w);                        \
        b0p[0] = tf32f(pb0.x); b0p[1] = tf32f(pb0.y);                        \
        b0p[2] = tf32f(pb0.z); b0p[3] = tf32f(pb0.w);                        \
        b1p[0] = tf32f(pb1.x); b1p[1] = tf32f(pb1.y);                        \
        b1p[2] = tf32f(pb1.z); b1p[3] = tf32f(pb1.w);                        \
    } while (0)

    LDG_STAGE(0);
    STS_STAGE(0);

    const int NSTAGE = KD_ / 16;   // 64
    for (int kt = 0; kt < NSTAGE; kt++) {
        __syncthreads();
        const int buf = kt & 1;
        if (kt + 1 < NSTAGE) LDG_STAGE(kt + 1);

#pragma unroll
        for (int kk = 0; kk < 16; kk += 8) {
            uint32_t af[4][4], bf[4][2];
#pragma unroll
            for (int mt = 0; mt < 4; mt++) {
                const int r = wm + mt * 16 + g;
                af[mt][0] = __float_as_uint(As[buf][r][kk + tg]);
                af[mt][1] = __float_as_uint(As[buf][r + 8][kk + tg]);
                af[mt][2] = __float_as_uint(As[buf][r][kk + tg + 4]);
                af[mt][3] = __float_as_uint(As[buf][r + 8][kk + tg + 4]);
            }
#pragma unroll
            for (int nt = 0; nt < 4; nt++) {
                const int c = wn + nt * 8 + g;
                bf[nt][0] = __float_as_uint(Bs[buf][c][kk + tg]);
                bf[nt][1] = __float_as_uint(Bs[buf][c][kk + tg + 4]);
            }
#pragma unroll
            for (int mt = 0; mt < 4; mt++)
#pragma unroll
                for (int nt = 0; nt < 4; nt++)
                    mma_tf32(d[mt][nt], af[mt], bf[nt]);
        }

        if (kt + 1 < NSTAGE) {
            __syncthreads();
            STS_STAGE(buf ^ 1);
        }
    }

#pragma unroll
    for (int mt = 0; mt < 4; mt++) {
        const int r = rowBase + wm + mt * 16 + g;
#pragma unroll
        for (int nt = 0; nt < 4; nt++) {
            const int c = colBase + wn + nt * 8 + 2 * tg;
            float* p = Cm + (size_t)r * N + c;
            *(float2*)p = make_float2(d[mt][nt][0], d[mt][nt][1]);
            *(float2*)(p + (size_t)8 * N) = make_float2(d[mt][nt][2], d[mt][nt][3]);
        }
    }
#undef LDG_STAGE
#undef STS_STAGE
}

// ===========================================================================
// Transpose: out[c][r] = in[r][c]
// ===========================================================================
__global__ void transposeK(const float* __restrict__ in, float* __restrict__ out,
                           int R, int Cc) {
    __shared__ float t[32][33];
    const int c0 = blockIdx.x * 32, r0 = blockIdx.y * 32;
    const int tx = threadIdx.x, ty = threadIdx.y;
#pragma unroll
    for (int i = 0; i < 32; i += 8)
        t[ty + i][tx] = in[(size_t)(r0 + ty + i) * Cc + c0 + tx];
    __syncthreads();
#pragma unroll
    for (int i = 0; i < 32; i += 8)
        out[(size_t)(c0 + ty + i) * R + r0 + tx] = t[tx][ty + i];
}

// ===========================================================================
// FP16 tensor-core causal flash attention (m16n8k16, fp32 accumulate).
// CTA = 128 queries x (b,h), 8 warps x 16 q-rows (warp-private). KV tile 64.
// fp16 keeps tf32's 10 mantissa bits but doubles FLOP/instr and halves smem.
// V stored d-major (transposed at load) so PV B-frags are contiguous half2.
// All pitches 72 halves: fragment banks = 4g+tg (conflict-free).
// Softmax in exp2 domain (scale*log2e folded into the one required FMUL).
// ===========================================================================
#define QTILE 128
#define KTILE 64
#define PH 72   // pitch in halves for all tiles
#define ATT_SMEM ((QTILE * PH + KTILE * PH + KTILE * PH + QTILE * PH) * 2)

__global__ __launch_bounds__(256, 2)
void attn_mma(const float* __restrict__ qkv, float* __restrict__ att) {
    extern __shared__ __half smh[];
    __half* Qs = smh;                     // [128][72]  q-major
    __half* Ks = Qs + QTILE * PH;         // [64][72]   key-major
    __half* Vt = Ks + KTILE * PH;         // [64][72]   d-major (transposed)
    __half* Ps = Vt + KTILE * PH;         // [128][72]  q-major

    const int qt = (int)gridDim.x - 1 - (int)blockIdx.x;  // heavy tiles first
    const int h = blockIdx.y, b = blockIdx.z;
    const int q0 = qt * QTILE;
    const int tid = threadIdx.x;
    const int lane = tid & 31, w = tid >> 5;
    const int g = lane >> 2, tg = lane & 3;

    const float* base = qkv + (size_t)b * T_ * N3_ + (size_t)h * D_;
    const float* qb = base;
    const float* kb = base + C_;
    const float* vb = base + 2 * C_;

    // Load Q tile [128 x 64] -> fp16 (8 float4 per thread)
#pragma unroll
    for (int e = 0; e < 8; e++) {
        int i4 = e * 256 + tid;
        int r = i4 >> 4, d4 = (i4 & 15) << 2;
        float4 v = *(const float4*)&qb[(size_t)(q0 + r) * N3_ + d4];
        __half2* p = (__half2*)&Qs[r * PH + d4];
        p[0] = __floats2half2_rn(v.x, v.y);
        p[1] = __floats2half2_rn(v.z, v.w);
    }

    float o[8][4];
#pragma unroll
    for (int nt = 0; nt < 8; nt++)
#pragma unroll
        for (int q = 0; q < 4; q++) o[nt][q] = 0.f;
    float m0 = -1e30f, m1 = -1e30f, l0 = 0.f, l1 = 0.f;

    const int rowA = 16 * w + g;
    const int rowB = rowA + 8;
    const float SC = 0.125f * 1.44269504089f;   // scale * log2(e)
    const int ntiles = 2 * qt + 2;

    for (int jt = 0; jt < ntiles; jt++) {
        const int k0 = jt * KTILE;
        __syncthreads();   // prior iter's K/V reads done (Q stores visible)

        // Load K [64x64] key-major and V transposed d-major (fp16)
#pragma unroll
        for (int e = 0; e < 4; e++) {
            int i4 = e * 256 + tid;
            int r = i4 >> 4, d4 = (i4 & 15) << 2;
            float4 kv = *(const float4*)&kb[(size_t)(k0 + r) * N3_ + d4];
            __half2* kp = (__half2*)&Ks[r * PH + d4];
            kp[0] = __floats2half2_rn(kv.x, kv.y);
            kp[1] = __floats2half2_rn(kv.z, kv.w);
            float4 vv = *(const float4*)&vb[(size_t)(k0 + r) * N3_ + d4];
            Vt[(d4 + 0) * PH + r] = __float2half_rn(vv.x);
            Vt[(d4 + 1) * PH + r] = __float2half_rn(vv.y);
            Vt[(d4 + 2) * PH + r] = __float2half_rn(vv.z);
            Vt[(d4 + 3) * PH + r] = __float2half_rn(vv.w);
        }
        __syncthreads();

        // ---- S = Q @ K^T (16 x 64 per warp), k16 chunks over D=64 ----
        float s[8][4];
#pragma unroll
        for (int nt = 0; nt < 8; nt++)
#pragma unroll
            for (int q = 0; q < 4; q++) s[nt][q] = 0.f;

#pragma unroll
        for (int kk = 0; kk < 4; kk++) {
            uint32_t a[4];
            a[0] = *(const uint32_t*)&Qs[rowA * PH + 16 * kk + 2 * tg];
            a[1] = *(const uint32_t*)&Qs[rowB * PH + 16 * kk + 2 * tg];
            a[2] = *(const uint32_t*)&Qs[rowA * PH + 16 * kk + 2 * tg + 8];
            a[3] = *(const uint32_t*)&Qs[rowB * PH + 16 * kk + 2 * tg + 8];
#pragma unroll
            for (int nt = 0; nt < 8; nt++) {
                uint32_t bb[2];
                bb[0] = *(const uint32_t*)&Ks[(8 * nt + g) * PH + 16 * kk + 2 * tg];
                bb[1] = *(const uint32_t*)&Ks[(8 * nt + g) * PH + 16 * kk + 2 * tg + 8];
                mma_f16(s[nt], a, bb);
            }
        }

        // ---- softmax (registers, exp2 domain, quad reductions) ----
        const bool masked = (jt >= 2 * qt);
        const int qr0 = q0 + rowA, qr1 = q0 + rowB;
        float rm0 = -1e30f, rm1 = -1e30f;
#pragma unroll
        for (int nt = 0; nt < 8; nt++) {
            const int key = k0 + 8 * nt + 2 * tg;
            s[nt][0] *= SC; s[nt][1] *= SC;
            s[nt][2] *= SC; s[nt][3] *= SC;
            if (masked) {
                if (key     > qr0) s[nt][0] = -1e30f;
                if (key + 1 > qr0) s[nt][1] = -1e30f;
                if (key     > qr1) s[nt][2] = -1e30f;
                if (key + 1 > qr1) s[nt][3] = -1e30f;
            }
            rm0 = fmaxf(rm0, fmaxf(s[nt][0], s[nt][1]));
            rm1 = fmaxf(rm1, fmaxf(s[nt][2], s[nt][3]));
        }
#pragma unroll
        for (int off = 1; off < 4; off <<= 1) {
            rm0 = fmaxf(rm0, __shfl_xor_sync(0xffffffffu, rm0, off));
            rm1 = fmaxf(rm1, __shfl_xor_sync(0xffffffffu, rm1, off));
        }
        const float mn0 = fmaxf(m0, rm0), mn1 = fmaxf(m1, rm1);
        const float al0 = exp2f(m0 - mn0), al1 = exp2f(m1 - mn1);
        m0 = mn0; m1 = mn1;

        float sum0 = 0.f, sum1 = 0.f;
#pragma unroll
        for (int nt = 0; nt < 8; nt++) {
            s[nt][0] = exp2f(s[nt][0] - mn0); sum0 += s[nt][0];
            s[nt][1] = exp2f(s[nt][1] - mn0); sum0 += s[nt][1];
            s[nt][2] = exp2f(s[nt][2] - mn1); sum1 += s[nt][2];
            s[nt][3] = exp2f(s[nt][3] - mn1); sum1 += s[nt][3];
        }
#pragma unroll
        for (int off = 1; off < 4; off <<= 1) {
            sum0 += __shfl_xor_sync(0xffffffffu, sum0, off);
            sum1 += __shfl_xor_sync(0xffffffffu, sum1, off);
        }
        l0 = l0 * al0 + sum0;
        l1 = l1 * al1 + sum1;
#pragma unroll
        for (int nt = 0; nt < 8; nt++) {
            o[nt][0] *= al0; o[nt][1] *= al0;
            o[nt][2] *= al1; o[nt][3] *= al1;
        }

        // ---- P -> warp-private smem (fp16), then O += P @ V ----
#pragma unroll
        for (int nt = 0; nt < 8; nt++) {
            *(__half2*)&Ps[rowA * PH + 8 * nt + 2 * tg] =
                __floats2half2_rn(s[nt][0], s[nt][1]);
            *(__half2*)&Ps[rowB * PH + 8 * nt + 2 * tg] =
                __floats2half2_rn(s[nt][2], s[nt][3]);
        }
        __syncwarp();

#pragma unroll
        for (int kk = 0; kk < 4; kk++) {       // k16 chunks over 64 keys
            uint32_t a[4];
            a[0] = *(const uint32_t*)&Ps[rowA * PH + 16 * kk + 2 * tg];
            a[1] = *(const uint32_t*)&Ps[rowB * PH + 16 * kk + 2 * tg];
            a[2] = *(const uint32_t*)&Ps[rowA * PH + 16 * kk + 2 * tg + 8];
            a[3] = *(const uint32_t*)&Ps[rowB * PH + 16 * kk + 2 * tg + 8];
#pragma unroll
            for (int nt = 0; nt < 8; nt++) {   // output d columns 8*nt..
                uint32_t bb[2];
                bb[0] = *(const uint32_t*)&Vt[(8 * nt + g) * PH + 16 * kk + 2 * tg];
                bb[1] = *(const uint32_t*)&Vt[(8 * nt + g) * PH + 16 * kk + 2 * tg + 8];
                mma_f16(o[nt], a, bb);
            }
        }
    }

    // Epilogue: normalize and store [B,T,C], head h at cols h*64.
    const float inv0 = 1.f / l0, inv1 = 1.f / l1;
    float* obA = att + ((size_t)(b * T_) + q0 + rowA) * C_ + (size_t)h * D_;
    float* obB = att + ((size_t)(b * T_) + q0 + rowB) * C_ + (size_t)h * D_;
#pragma unroll
    for (int nt = 0; nt < 8; nt++) {
        const int c = 8 * nt + 2 * tg;
        *(float2*)(obA + c) = make_float2(o[nt][0] * inv0, o[nt][1] * inv0);
        *(float2*)(obB + c) = make_float2(o[nt][2] * inv1, o[nt][3] * inv1);
    }
}

// ===========================================================================
// Launch
// ===========================================================================
extern "C" void kernel_launch(void* const* d_in, const int* in_sizes, int n_in,
                              void* d_out, int out_size) {
    const float* x      = (const float*)d_in[0];
    const float* w_qkv  = (const float*)d_in[1];
    const float* w_proj = (const float*)d_in[2];
    float* out = (float*)d_out;

    void *qkv_p, *att_p, *wqkvT_p, *wprojT_p;
    cudaGetSymbolAddress(&qkv_p, g_qkv);
    cudaGetSymbolAddress(&att_p, g_att);
    cudaGetSymbolAddress(&wqkvT_p, g_wqkvT);
    cudaGetSymbolAddress(&wprojT_p, g_wprojT);
    float* qkv    = (float*)qkv_p;
    float* att    = (float*)att_p;
    float* wqkvT  = (float*)wqkvT_p;
    float* wprojT = (float*)wprojT_p;

    cudaFuncSetAttribute(attn_mma, cudaFuncAttributeMaxDynamicSharedMemorySize,
                         ATT_SMEM);

    transposeK<<<dim3(N3_ / 32, KD_ / 32), dim3(32, 8)>>>(w_qkv, wqkvT, KD_, N3_);
    transposeK<<<dim3(C_ / 32, KD_ / 32), dim3(32, 8)>>>(w_proj, wprojT, KD_, C_);

    gemm_mma<<<dim3(N3_ / 128, M_ / 128), 256>>>(x, wqkvT, qkv, N3_);
    attn_mma<<<dim3(T_ / QTILE, H_, B_), 256, ATT_SMEM>>>(qkv, att);
    gemm_mma<<<dim3(C_ / 128, M_ / 128), 256>>>(att, wprojT, out, C_);
}

// round 11
// speedup vs baseline: 4.6738x; 1.3954x over previous
#include <cuda_runtime.h>
#include <cuda_fp16.h>
#include <cstdint>
#include <cstddef>

#define B_  4
#define T_  2048
#define C_  1024
#define H_  16
#define D_  64
#define M_  (B_ * T_)        // 8192
#define N3_ (3 * C_)         // 3072
#define KD_ 1024

// Scratch (static device globals — no allocation in kernel_launch)
__device__ __align__(16) float g_qkv[(size_t)M_ * N3_];     // [B*T, 3C]
__device__ __align__(16) float g_att[(size_t)M_ * C_];      // [B*T, C]
__device__ __align__(16) float g_wqkvT[(size_t)N3_ * KD_];  // w_qkv^T  [N,K]
__device__ __align__(16) float g_wprojT[(size_t)C_ * KD_];  // w_proj^T [N,K]

// mma.sync m16n8k16 fp16 with fp32 accumulate
__device__ __forceinline__ void mma_f16(float d[4], const uint32_t a[4],
                                        const uint32_t b[2]) {
    asm volatile(
        "mma.sync.aligned.m16n8k16.row.col.f32.f16.f16.f32 "
        "{%0,%1,%2,%3}, {%4,%5,%6,%7}, {%8,%9}, {%0,%1,%2,%3};"
        : "+f"(d[0]), "+f"(d[1]), "+f"(d[2]), "+f"(d[3])
        : "r"(a[0]), "r"(a[1]), "r"(a[2]), "r"(a[3]), "r"(b[0]), "r"(b[1]));
}

// ===========================================================================
// FP16 tensor-core GEMM: Cm[M,N] = A[M,1024] @ BT[N,1024]^T
// CTA tile 128x128, BK=32 (2 x m16n8k16 k-chunks/stage), double-buffered
// half smem, pitch 40 halves (fragment banks (20g+tg)%32 all distinct).
// fp32->fp16 conversion on the LDG->STS path (same mantissa as tf32).
// 8 warps, 64x32 warp tile, fp32 accumulators.
// ===========================================================================
#define PHG 40            // pitch in halves
#define NSTAGE (KD_ / 32) // 32

__global__ __launch_bounds__(256, 2)
void gemm_mma(const float* __restrict__ A, const float* __restrict__ BT,
              float* __restrict__ Cm, int N) {
    __shared__ __half As[2][128][PHG];
    __shared__ __half Bs[2][128][PHG];

    const int tid = threadIdx.x;
    const int lane = tid & 31, wid = tid >> 5;
    const int g = lane >> 2, tg = lane & 3;
    const int wm = (wid & 1) * 64;
    const int wn = (wid >> 1) * 32;
    const int rowBase = blockIdx.y * 128;
    const int colBase = blockIdx.x * 128;

    // Stage-load addressing: rows tid>>3 + {0,32,64,96}, col (tid&7)*4.
    const int r0l = tid >> 3;            // 0..31
    const int c0l = (tid & 7) << 2;      // 0..28
    const float* Ap = A + (size_t)(rowBase + r0l) * KD_ + c0l;
    const float* Bp = BT + (size_t)(colBase + r0l) * KD_ + c0l;

    float d[4][4][4];
#pragma unroll
    for (int mt = 0; mt < 4; mt++)
#pragma unroll
        for (int nt = 0; nt < 4; nt++)
#pragma unroll
            for (int q = 0; q < 4; q++) d[mt][nt][q] = 0.f;

    float4 pa[4], pb[4];

#define LDG_STAGE(kt)                                                         \
    do {                                                                      \
        _Pragma("unroll")                                                     \
        for (int e = 0; e < 4; e++) {                                         \
            pa[e] = *(const float4*)(Ap + (size_t)(e * 32) * KD_ + (kt) * 32);\
            pb[e] = *(const float4*)(Bp + (size_t)(e * 32) * KD_ + (kt) * 32);\
        }                                                                     \
    } while (0)

#define STS_STAGE(buf)                                                       \
    do {                                                                     \
        _Pragma("unroll")                                                    \
        for (int e = 0; e < 4; e++) {                                        \
            __half2* ap = (__half2*)&As[buf][r0l + e * 32][c0l];             \
            ap[0] = __floats2half2_rn(pa[e].x, pa[e].y);                     \
            ap[1] = __floats2half2_rn(pa[e].z, pa[e].w);                     \
            __half2* bp = (__half2*)&Bs[buf][r0l + e * 32][c0l];             \
            bp[0] = __floats2half2_rn(pb[e].x, pb[e].y);                     \
            bp[1] = __floats2half2_rn(pb[e].z, pb[e].w);                     \
        }                                                                    \
    } while (0)

    LDG_STAGE(0);
    STS_STAGE(0);

    for (int kt = 0; kt < NSTAGE; kt++) {
        __syncthreads();           // stage kt stores visible; prior reads done
        const int buf = kt & 1;
        if (kt + 1 < NSTAGE) LDG_STAGE(kt + 1);

#pragma unroll
        for (int kk = 0; kk < 2; kk++) {   // two k16 chunks in BK=32
            uint32_t af[4][4], bf[4][2];
#pragma unroll
            for (int mt = 0; mt < 4; mt++) {
                const int r = wm + mt * 16 + g;
                af[mt][0] = *(const uint32_t*)&As[buf][r][16 * kk + 2 * tg];
                af[mt][1] = *(const uint32_t*)&As[buf][r + 8][16 * kk + 2 * tg];
                af[mt][2] = *(const uint32_t*)&As[buf][r][16 * kk + 2 * tg + 8];
                af[mt][3] = *(const uint32_t*)&As[buf][r + 8][16 * kk + 2 * tg + 8];
            }
#pragma unroll
            for (int nt = 0; nt < 4; nt++) {
                const int c = wn + nt * 8 + g;
                bf[nt][0] = *(const uint32_t*)&Bs[buf][c][16 * kk + 2 * tg];
                bf[nt][1] = *(const uint32_t*)&Bs[buf][c][16 * kk + 2 * tg + 8];
            }
#pragma unroll
            for (int mt = 0; mt < 4; mt++)
#pragma unroll
                for (int nt = 0; nt < 4; nt++)
                    mma_f16(d[mt][nt], af[mt], bf[nt]);
        }

        if (kt + 1 < NSTAGE) {
            __syncthreads();       // all warps done reading buf^1
            STS_STAGE(buf ^ 1);
        }
    }

#pragma unroll
    for (int mt = 0; mt < 4; mt++) {
        const int r = rowBase + wm + mt * 16 + g;
#pragma unroll
        for (int nt = 0; nt < 4; nt++) {
            const int c = colBase + wn + nt * 8 + 2 * tg;
            float* p = Cm + (size_t)r * N + c;
            *(float2*)p = make_float2(d[mt][nt][0], d[mt][nt][1]);
            *(float2*)(p + (size_t)8 * N) = make_float2(d[mt][nt][2], d[mt][nt][3]);
        }
    }
#undef LDG_STAGE
#undef STS_STAGE
}

// ===========================================================================
// Transpose: out[c][r] = in[r][c]
// ===========================================================================
__global__ void transposeK(const float* __restrict__ in, float* __restrict__ out,
                           int R, int Cc) {
    __shared__ float t[32][33];
    const int c0 = blockIdx.x * 32, r0 = blockIdx.y * 32;
    const int tx = threadIdx.x, ty = threadIdx.y;
#pragma unroll
    for (int i = 0; i < 32; i += 8)
        t[ty + i][tx] = in[(size_t)(r0 + ty + i) * Cc + c0 + tx];
    __syncthreads();
#pragma unroll
    for (int i = 0; i < 32; i += 8)
        out[(size_t)(c0 + ty + i) * R + r0 + tx] = t[tx][ty + i];
}

// ===========================================================================
// FP16 tensor-core causal flash attention (m16n8k16, fp32 accumulate).
// (unchanged from passing round 10)
// ===========================================================================
#define QTILE 128
#define KTILE 64
#define PH 72   // pitch in halves for all tiles
#define ATT_SMEM ((QTILE * PH + KTILE * PH + KTILE * PH + QTILE * PH) * 2)

__global__ __launch_bounds__(256, 2)
void attn_mma(const float* __restrict__ qkv, float* __restrict__ att) {
    extern __shared__ __half smh[];
    __half* Qs = smh;                     // [128][72]  q-major
    __half* Ks = Qs + QTILE * PH;         // [64][72]   key-major
    __half* Vt = Ks + KTILE * PH;         // [64][72]   d-major (transposed)
    __half* Ps = Vt + KTILE * PH;         // [128][72]  q-major

    const int qt = (int)gridDim.x - 1 - (int)blockIdx.x;  // heavy tiles first
    const int h = blockIdx.y, b = blockIdx.z;
    const int q0 = qt * QTILE;
    const int tid = threadIdx.x;
    const int lane = tid & 31, w = tid >> 5;
    const int g = lane >> 2, tg = lane & 3;

    const float* base = qkv + (size_t)b * T_ * N3_ + (size_t)h * D_;
    const float* qb = base;
    const float* kb = base + C_;
    const float* vb = base + 2 * C_;

    // Load Q tile [128 x 64] -> fp16 (8 float4 per thread)
#pragma unroll
    for (int e = 0; e < 8; e++) {
        int i4 = e * 256 + tid;
        int r = i4 >> 4, d4 = (i4 & 15) << 2;
        float4 v = *(const float4*)&qb[(size_t)(q0 + r) * N3_ + d4];
        __half2* p = (__half2*)&Qs[r * PH + d4];
        p[0] = __floats2half2_rn(v.x, v.y);
        p[1] = __floats2half2_rn(v.z, v.w);
    }

    float o[8][4];
#pragma unroll
    for (int nt = 0; nt < 8; nt++)
#pragma unroll
        for (int q = 0; q < 4; q++) o[nt][q] = 0.f;
    float m0 = -1e30f, m1 = -1e30f, l0 = 0.f, l1 = 0.f;

    const int rowA = 16 * w + g;
    const int rowB = rowA + 8;
    const float SC = 0.125f * 1.44269504089f;   // scale * log2(e)
    const int ntiles = 2 * qt + 2;

    for (int jt = 0; jt < ntiles; jt++) {
        const int k0 = jt * KTILE;
        __syncthreads();   // prior iter's K/V reads done (Q stores visible)

        // Load K [64x64] key-major and V transposed d-major (fp16)
#pragma unroll
        for (int e = 0; e < 4; e++) {
            int i4 = e * 256 + tid;
            int r = i4 >> 4, d4 = (i4 & 15) << 2;
            float4 kv = *(const float4*)&kb[(size_t)(k0 + r) * N3_ + d4];
            __half2* kp = (__half2*)&Ks[r * PH + d4];
            kp[0] = __floats2half2_rn(kv.x, kv.y);
            kp[1] = __floats2half2_rn(kv.z, kv.w);
            float4 vv = *(const float4*)&vb[(size_t)(k0 + r) * N3_ + d4];
            Vt[(d4 + 0) * PH + r] = __float2half_rn(vv.x);
            Vt[(d4 + 1) * PH + r] = __float2half_rn(vv.y);
            Vt[(d4 + 2) * PH + r] = __float2half_rn(vv.z);
            Vt[(d4 + 3) * PH + r] = __float2half_rn(vv.w);
        }
        __syncthreads();

        // ---- S = Q @ K^T (16 x 64 per warp), k16 chunks over D=64 ----
        float s[8][4];
#pragma unroll
        for (int nt = 0; nt < 8; nt++)
#pragma unroll
            for (int q = 0; q < 4; q++) s[nt][q] = 0.f;

#pragma unroll
        for (int kk = 0; kk < 4; kk++) {
            uint32_t a[4];
            a[0] = *(const uint32_t*)&Qs[rowA * PH + 16 * kk + 2 * tg];
            a[1] = *(const uint32_t*)&Qs[rowB * PH + 16 * kk + 2 * tg];
            a[2] = *(const uint32_t*)&Qs[rowA * PH + 16 * kk + 2 * tg + 8];
            a[3] = *(const uint32_t*)&Qs[rowB * PH + 16 * kk + 2 * tg + 8];
#pragma unroll
            for (int nt = 0; nt < 8; nt++) {
                uint32_t bb[2];
                bb[0] = *(const uint32_t*)&Ks[(8 * nt + g) * PH + 16 * kk + 2 * tg];
                bb[1] = *(const uint32_t*)&Ks[(8 * nt + g) * PH + 16 * kk + 2 * tg + 8];
                mma_f16(s[nt], a, bb);
            }
        }

        // ---- softmax (registers, exp2 domain, quad reductions) ----
        const bool masked = (jt >= 2 * qt);
        const int qr0 = q0 + rowA, qr1 = q0 + rowB;
        float rm0 = -1e30f, rm1 = -1e30f;
#pragma unroll
        for (int nt = 0; nt < 8; nt++) {
            const int key = k0 + 8 * nt + 2 * tg;
            s[nt][0] *= SC; s[nt][1] *= SC;
            s[nt][2] *= SC; s[nt][3] *= SC;
            if (masked) {
                if (key     > qr0) s[nt][0] = -1e30f;
                if (key + 1 > qr0) s[nt][1] = -1e30f;
                if (key     > qr1) s[nt][2] = -1e30f;
                if (key + 1 > qr1) s[nt][3] = -1e30f;
            }
            rm0 = fmaxf(rm0, fmaxf(s[nt][0], s[nt][1]));
            rm1 = fmaxf(rm1, fmaxf(s[nt][2], s[nt][3]));
        }
#pragma unroll
        for (int off = 1; off < 4; off <<= 1) {
            rm0 = fmaxf(rm0, __shfl_xor_sync(0xffffffffu, rm0, off));
            rm1 = fmaxf(rm1, __shfl_xor_sync(0xffffffffu, rm1, off));
        }
        const float mn0 = fmaxf(m0, rm0), mn1 = fmaxf(m1, rm1);
        const float al0 = exp2f(m0 - mn0), al1 = exp2f(m1 - mn1);
        m0 = mn0; m1 = mn1;

        float sum0 = 0.f, sum1 = 0.f;
#pragma unroll
        for (int nt = 0; nt < 8; nt++) {
            s[nt][0] = exp2f(s[nt][0] - mn0); sum0 += s[nt][0];
            s[nt][1] = exp2f(s[nt][1] - mn0); sum0 += s[nt][1];
            s[nt][2] = exp2f(s[nt][2] - mn1); sum1 += s[nt][2];
            s[nt][3] = exp2f(s[nt][3] - mn1); sum1 += s[nt][3];
        }
#pragma unroll
        for (int off = 1; off < 4; off <<= 1) {
            sum0 += __shfl_xor_sync(0xffffffffu, sum0, off);
            sum1 += __shfl_xor_sync(0xffffffffu, sum1, off);
        }
        l0 = l0 * al0 + sum0;
        l1 = l1 * al1 + sum1;
#pragma unroll
        for (int nt = 0; nt < 8; nt++) {
            o[nt][0] *= al0; o[nt][1] *= al0;
            o[nt][2] *= al1; o[nt][3] *= al1;
        }

        // ---- P -> warp-private smem (fp16), then O += P @ V ----
#pragma unroll
        for (int nt = 0; nt < 8; nt++) {
            *(__half2*)&Ps[rowA * PH + 8 * nt + 2 * tg] =
                __floats2half2_rn(s[nt][0], s[nt][1]);
            *(__half2*)&Ps[rowB * PH + 8 * nt + 2 * tg] =
                __floats2half2_rn(s[nt][2], s[nt][3]);
        }
        __syncwarp();

#pragma unroll
        for (int kk = 0; kk < 4; kk++) {       // k16 chunks over 64 keys
            uint32_t a[4];
            a[0] = *(const uint32_t*)&Ps[rowA * PH + 16 * kk + 2 * tg];
            a[1] = *(const uint32_t*)&Ps[rowB * PH + 16 * kk + 2 * tg];
            a[2] = *(const uint32_t*)&Ps[rowA * PH + 16 * kk + 2 * tg + 8];
            a[3] = *(const uint32_t*)&Ps[rowB * PH + 16 * kk + 2 * tg + 8];
#pragma unroll
            for (int nt = 0; nt < 8; nt++) {   // output d columns 8*nt..
                uint32_t bb[2];
                bb[0] = *(const uint32_t*)&Vt[(8 * nt + g) * PH + 16 * kk + 2 * tg];
                bb[1] = *(const uint32_t*)&Vt[(8 * nt + g) * PH + 16 * kk + 2 * tg + 8];
                mma_f16(o[nt], a, bb);
            }
        }
    }

    // Epilogue: normalize and store [B,T,C], head h at cols h*64.
    const float inv0 = 1.f / l0, inv1 = 1.f / l1;
    float* obA = att + ((size_t)(b * T_) + q0 + rowA) * C_ + (size_t)h * D_;
    float* obB = att + ((size_t)(b * T_) + q0 + rowB) * C_ + (size_t)h * D_;
#pragma unroll
    for (int nt = 0; nt < 8; nt++) {
        const int c = 8 * nt + 2 * tg;
        *(float2*)(obA + c) = make_float2(o[nt][0] * inv0, o[nt][1] * inv0);
        *(float2*)(obB + c) = make_float2(o[nt][2] * inv1, o[nt][3] * inv1);
    }
}

// ===========================================================================
// Launch
// ===========================================================================
extern "C" void kernel_launch(void* const* d_in, const int* in_sizes, int n_in,
                              void* d_out, int out_size) {
    const float* x      = (const float*)d_in[0];
    const float* w_qkv  = (const float*)d_in[1];
    const float* w_proj = (const float*)d_in[2];
    float* out = (float*)d_out;

    void *qkv_p, *att_p, *wqkvT_p, *wprojT_p;
    cudaGetSymbolAddress(&qkv_p, g_qkv);
    cudaGetSymbolAddress(&att_p, g_att);
    cudaGetSymbolAddress(&wqkvT_p, g_wqkvT);
    cudaGetSymbolAddress(&wprojT_p, g_wprojT);
    float* qkv    = (float*)qkv_p;
    float* att    = (float*)att_p;
    float* wqkvT  = (float*)wqkvT_p;
    float* wprojT = (float*)wprojT_p;

    cudaFuncSetAttribute(attn_mma, cudaFuncAttributeMaxDynamicSharedMemorySize,
                         ATT_SMEM);

    transposeK<<<dim3(N3_ / 32, KD_ / 32), dim3(32, 8)>>>(w_qkv, wqkvT, KD_, N3_);
    transposeK<<<dim3(C_ / 32, KD_ / 32), dim3(32, 8)>>>(w_proj, wprojT, KD_, C_);

    gemm_mma<<<dim3(N3_ / 128, M_ / 128), 256>>>(x, wqkvT, qkv, N3_);
    attn_mma<<<dim3(T_ / QTILE, H_, B_), 256, ATT_SMEM>>>(qkv, att);
    gemm_mma<<<dim3(C_ / 128, M_ / 128), 256>>>(att, wprojT, out, C_);
}

// round 14
// speedup vs baseline: 4.9109x; 1.0507x over previous
#include <cuda_runtime.h>
#include <cuda_fp16.h>
#include <cstdint>
#include <cstddef>

#define B_  4
#define T_  2048
#define C_  1024
#define H_  16
#define D_  64
#define M_  (B_ * T_)        // 8192
#define N3_ (3 * C_)         // 3072
#define KD_ 1024

// Scratch (static device globals — no allocation in kernel_launch).
__device__ __align__(16) __half g_qkv[(size_t)M_ * N3_];     // [B*T, 3C]
__device__ __align__(16) __half g_att[(size_t)M_ * C_];      // [B*T, C]
__device__ __align__(16) __half g_wqkvT[(size_t)N3_ * KD_];  // w_qkv^T  [N,K]
__device__ __align__(16) __half g_wprojT[(size_t)C_ * KD_];  // w_proj^T [N,K]

// mma.sync m16n8k16 fp16 with fp32 accumulate
__device__ __forceinline__ void mma_f16(float d[4], const uint32_t a[4],
                                        const uint32_t b[2]) {
    asm volatile(
        "mma.sync.aligned.m16n8k16.row.col.f32.f16.f16.f32 "
        "{%0,%1,%2,%3}, {%4,%5,%6,%7}, {%8,%9}, {%0,%1,%2,%3};"
        : "+f"(d[0]), "+f"(d[1]), "+f"(d[2]), "+f"(d[3])
        : "r"(a[0]), "r"(a[1]), "r"(a[2]), "r"(a[3]), "r"(b[0]), "r"(b[1]));
}

__device__ __forceinline__ void ldsm_x4(uint32_t& r0, uint32_t& r1,
                                        uint32_t& r2, uint32_t& r3,
                                        uint32_t addr) {
    asm volatile("ldmatrix.sync.aligned.m8n8.x4.shared.b16 {%0,%1,%2,%3}, [%4];"
                 : "=r"(r0), "=r"(r1), "=r"(r2), "=r"(r3) : "r"(addr));
}
__device__ __forceinline__ uint32_t smem_u32(const void* p) {
    return (uint32_t)__cvta_generic_to_shared(p);
}

// ===========================================================================
// FP16 tensor-core GEMM with ldmatrix fragments.
// Cm[M,N] = A[M,1024] @ BT[N,1024]^T. CTA 128x128, BK=32, double-buffered,
// pitch 40 halves (ldmatrix row starts 20r mod 32: conflict-free).
// FIXED: stage copies now move 16 halves/thread/operand as TWO uint4
// (uint4 = 8 halves, not 16 — the R12/R13 NaN source was uninitialized smem).
// ===========================================================================
#define PHG 40            // pitch in halves
#define NSTAGE (KD_ / 32) // 32
#define GBUF (128 * PHG * 2)  // bytes per buffer

template <typename TA, typename TC>
__global__ __launch_bounds__(256, 2)
void gemm_mma(const TA* __restrict__ A, const __half* __restrict__ BT,
              TC* __restrict__ Cm, int N) {
    __shared__ __half As[2][128][PHG];
    __shared__ __half Bs[2][128][PHG];

    const int tid = threadIdx.x;
    const int lane = tid & 31, wid = tid >> 5;
    const int g = lane >> 2, tg = lane & 3;
    const int wm = (wid & 1) * 64;
    const int wn = (wid >> 1) * 32;
    const int rowBase = blockIdx.y * 128;
    const int colBase = blockIdx.x * 128;

    const uint32_t as_u = smem_u32(&As[0][0][0]);
    const uint32_t bs_u = smem_u32(&Bs[0][0][0]);
    // ldmatrix per-lane offsets (bytes)
    const uint32_t aOff =
        ((wm + (lane & 15)) * PHG + 8 * ((lane >> 4) & 1)) * 2;
    const uint32_t bOff =
        ((wn + (lane & 7) + ((lane & 16) >> 1)) * PHG + ((lane & 8) ? 8 : 0)) * 2;

    // Stage copy addressing: 2 threads per 128-half... per 32-half row chunk.
    const int rowL = tid >> 1;           // 0..127
    const int cbL  = (tid & 1) * 16;     // 0 or 16
    const __half* Bp = BT + (size_t)(colBase + rowL) * KD_ + cbL;
    const float* Apf = nullptr;
    const __half* Aph = nullptr;
    if constexpr (sizeof(TA) == 4)
        Apf = (const float*)A + (size_t)(rowBase + (tid >> 3)) * KD_ + ((tid & 7) << 2);
    else
        Aph = (const __half*)A + (size_t)(rowBase + rowL) * KD_ + cbL;

    float d[4][4][4];
#pragma unroll
    for (int mt = 0; mt < 4; mt++)
#pragma unroll
        for (int nt = 0; nt < 4; nt++)
#pragma unroll
            for (int q = 0; q < 4; q++) d[mt][nt][q] = 0.f;

    float4 pa[4];
    uint4 ua0, ua1, ub0, ub1;

#define LDG_STAGE(kt)                                                          \
    do {                                                                       \
        if constexpr (sizeof(TA) == 4) {                                       \
            _Pragma("unroll")                                                  \
            for (int e = 0; e < 4; e++)                                        \
                pa[e] = *(const float4*)(Apf + (size_t)(e * 32) * KD_ + (kt) * 32); \
        } else {                                                               \
            ua0 = *(const uint4*)(Aph + (kt) * 32);                            \
            ua1 = *(const uint4*)(Aph + (kt) * 32 + 8);                        \
        }                                                                      \
        ub0 = *(const uint4*)(Bp + (kt) * 32);                                 \
        ub1 = *(const uint4*)(Bp + (kt) * 32 + 8);                             \
    } while (0)

#define STS_STAGE(buf)                                                        \
    do {                                                                      \
        if constexpr (sizeof(TA) == 4) {                                      \
            _Pragma("unroll")                                                 \
            for (int e = 0; e < 4; e++) {                                     \
                __half2* ap = (__half2*)&As[buf][(tid >> 3) + e * 32][(tid & 7) << 2]; \
                ap[0] = __floats2half2_rn(pa[e].x, pa[e].y);                  \
                ap[1] = __floats2half2_rn(pa[e].z, pa[e].w);                  \
            }                                                                 \
        } else {                                                              \
            *(uint4*)&As[buf][rowL][cbL] = ua0;                               \
            *(uint4*)&As[buf][rowL][cbL + 8] = ua1;                           \
        }                                                                     \
        *(uint4*)&Bs[buf][rowL][cbL] = ub0;                                   \
        *(uint4*)&Bs[buf][rowL][cbL + 8] = ub1;                               \
    } while (0)

    LDG_STAGE(0);
    STS_STAGE(0);

    for (int kt = 0; kt < NSTAGE; kt++) {
        __syncthreads();
        const int buf = kt & 1;
        const uint32_t abase = as_u + buf * GBUF;
        const uint32_t bbase = bs_u + buf * GBUF;
        if (kt + 1 < NSTAGE) LDG_STAGE(kt + 1);

#pragma unroll
        for (int kk = 0; kk < 2; kk++) {
            uint32_t af[4][4], bf[4][2];
#pragma unroll
            for (int mt = 0; mt < 4; mt++)
                ldsm_x4(af[mt][0], af[mt][1], af[mt][2], af[mt][3],
                        abase + aOff + mt * (16 * PHG * 2) + kk * 32);
#pragma unroll
            for (int p = 0; p < 2; p++)
                ldsm_x4(bf[2 * p][0], bf[2 * p][1], bf[2 * p + 1][0], bf[2 * p + 1][1],
                        bbase + bOff + p * (16 * PHG * 2) + kk * 32);
#pragma unroll
            for (int mt = 0; mt < 4; mt++)
#pragma unroll
                for (int nt = 0; nt < 4; nt++)
                    mma_f16(d[mt][nt], af[mt], bf[nt]);
        }

        if (kt + 1 < NSTAGE) {
            __syncthreads();
            STS_STAGE(buf ^ 1);
        }
    }

    // Epilogue
#pragma unroll
    for (int mt = 0; mt < 4; mt++) {
        const int r = rowBase + wm + mt * 16 + g;
#pragma unroll
        for (int nt = 0; nt < 4; nt++) {
            const int c = colBase + wn + nt * 8 + 2 * tg;
            if constexpr (sizeof(TC) == 4) {
                float* p = (float*)Cm + (size_t)r * N + c;
                *(float2*)p = make_float2(d[mt][nt][0], d[mt][nt][1]);
                *(float2*)(p + (size_t)8 * N) =
                    make_float2(d[mt][nt][2], d[mt][nt][3]);
            } else {
                __half* p = (__half*)Cm + (size_t)r * N + c;
                *(__half2*)p = __floats2half2_rn(d[mt][nt][0], d[mt][nt][1]);
                *(__half2*)(p + (size_t)8 * N) =
                    __floats2half2_rn(d[mt][nt][2], d[mt][nt][3]);
            }
        }
    }
#undef LDG_STAGE
#undef STS_STAGE
}

// ===========================================================================
// Transpose + fp16 convert: out[c][r] = half(in[r][c])
// ===========================================================================
__global__ void transposeK(const float* __restrict__ in, __half* __restrict__ out,
                           int R, int Cc) {
    __shared__ float t[32][33];
    const int c0 = blockIdx.x * 32, r0 = blockIdx.y * 32;
    const int tx = threadIdx.x, ty = threadIdx.y;
#pragma unroll
    for (int i = 0; i < 32; i += 8)
        t[ty + i][tx] = in[(size_t)(r0 + ty + i) * Cc + c0 + tx];
    __syncthreads();
#pragma unroll
    for (int i = 0; i < 32; i += 8)
        out[(size_t)(c0 + ty + i) * R + r0 + tx] = __float2half_rn(t[tx][ty + i]);
}

// ===========================================================================
// FP16 flash attention — R11-proven scalar fragment loads, fp16 gmem with
// CORRECTED uint4 copies (8 halves each, full tile coverage).
// CTA = 128 queries x (b,h), 8 warps x 16 q-rows. KV tile 64.
// V stored d-major (transposed at load). PH=72 pitches (proven conflict-free).
// ===========================================================================
#define QTILE 128
#define KTILE 64
#define PH 72   // pitch in halves for all tiles
#define ATT_SMEM ((QTILE * PH + KTILE * PH + KTILE * PH + QTILE * PH) * 2)

__global__ __launch_bounds__(256, 2)
void attn_mma(const __half* __restrict__ qkv, __half* __restrict__ att) {
    extern __shared__ __half smh[];
    __half* Qs = smh;                     // [128][72]  q-major
    __half* Ks = Qs + QTILE * PH;         // [64][72]   key-major
    __half* Vt = Ks + KTILE * PH;         // [64][72]   d-major (transposed)
    __half* Ps = Vt + KTILE * PH;         // [128][72]  q-major

    const int qt = (int)gridDim.x - 1 - (int)blockIdx.x;  // heavy tiles first
    const int h = blockIdx.y, b = blockIdx.z;
    const int q0 = qt * QTILE;
    const int tid = threadIdx.x;
    const int lane = tid & 31, w = tid >> 5;
    const int g = lane >> 2, tg = lane & 3;

    const __half* base = qkv + (size_t)b * T_ * N3_ + (size_t)h * D_;
    const __half* qb = base;
    const __half* kb = base + C_;
    const __half* vb = base + 2 * C_;

    // Load Q tile [128 x 64] = 1024 uint4 -> 4 per thread (8 halves each)
#pragma unroll
    for (int e = 0; e < 4; e++) {
        int i4 = e * 256 + tid;
        int r = i4 >> 3, sg = (i4 & 7) << 3;
        *(uint4*)&Qs[r * PH + sg] = *(const uint4*)&qb[(size_t)(q0 + r) * N3_ + sg];
    }

    float o[8][4];
#pragma unroll
    for (int nt = 0; nt < 8; nt++)
#pragma unroll
        for (int q = 0; q < 4; q++) o[nt][q] = 0.f;
    float m0 = -1e30f, m1 = -1e30f, l0 = 0.f, l1 = 0.f;

    const int rowA = 16 * w + g;
    const int rowB = rowA + 8;
    const float SC = 0.125f * 1.44269504089f;   // scale * log2(e)
    const int ntiles = 2 * qt + 2;

    for (int jt = 0; jt < ntiles; jt++) {
        const int k0 = jt * KTILE;
        __syncthreads();   // prior iter's K/V reads done (Q stores visible)

        // K [64x64] key-major raw (512 uint4 -> 2/thread);
        // V transposed to d-major (8 scalar halves per uint4).
#pragma unroll
        for (int e = 0; e < 2; e++) {
            int i4 = e * 256 + tid;
            int r = i4 >> 3, sg = (i4 & 7) << 3;
            *(uint4*)&Ks[r * PH + sg] = *(const uint4*)&kb[(size_t)(k0 + r) * N3_ + sg];
            uint4 uv = *(const uint4*)&vb[(size_t)(k0 + r) * N3_ + sg];
            const __half* hv = (const __half*)&uv;
#pragma unroll
            for (int i = 0; i < 8; i++)
                Vt[(sg + i) * PH + r] = hv[i];
        }
        __syncthreads();

        // ---- S = Q @ K^T (16 x 64 per warp), scalar fragments (R11) ----
        float s[8][4];
#pragma unroll
        for (int nt = 0; nt < 8; nt++)
#pragma unroll
            for (int q = 0; q < 4; q++) s[nt][q] = 0.f;

#pragma unroll
        for (int kk = 0; kk < 4; kk++) {
            uint32_t a[4];
            a[0] = *(const uint32_t*)&Qs[rowA * PH + 16 * kk + 2 * tg];
            a[1] = *(const uint32_t*)&Qs[rowB * PH + 16 * kk + 2 * tg];
            a[2] = *(const uint32_t*)&Qs[rowA * PH + 16 * kk + 2 * tg + 8];
            a[3] = *(const uint32_t*)&Qs[rowB * PH + 16 * kk + 2 * tg + 8];
#pragma unroll
            for (int nt = 0; nt < 8; nt++) {
                uint32_t bb[2];
                bb[0] = *(const uint32_t*)&Ks[(8 * nt + g) * PH + 16 * kk + 2 * tg];
                bb[1] = *(const uint32_t*)&Ks[(8 * nt + g) * PH + 16 * kk + 2 * tg + 8];
                mma_f16(s[nt], a, bb);
            }
        }

        // ---- softmax (registers, exp2 domain, quad reductions) ----
        const bool masked = (jt >= 2 * qt);
        const int qr0 = q0 + rowA, qr1 = q0 + rowB;
        float rm0 = -1e30f, rm1 = -1e30f;
#pragma unroll
        for (int nt = 0; nt < 8; nt++) {
            const int key = k0 + 8 * nt + 2 * tg;
            s[nt][0] *= SC; s[nt][1] *= SC;
            s[nt][2] *= SC; s[nt][3] *= SC;
            if (masked) {
                if (key     > qr0) s[nt][0] = -1e30f;
                if (key + 1 > qr0) s[nt][1] = -1e30f;
                if (key     > qr1) s[nt][2] = -1e30f;
                if (key + 1 > qr1) s[nt][3] = -1e30f;
            }
            rm0 = fmaxf(rm0, fmaxf(s[nt][0], s[nt][1]));
            rm1 = fmaxf(rm1, fmaxf(s[nt][2], s[nt][3]));
        }
#pragma unroll
        for (int off = 1; off < 4; off <<= 1) {
            rm0 = fmaxf(rm0, __shfl_xor_sync(0xffffffffu, rm0, off));
            rm1 = fmaxf(rm1, __shfl_xor_sync(0xffffffffu, rm1, off));
        }
        const float mn0 = fmaxf(m0, rm0), mn1 = fmaxf(m1, rm1);
        const float al0 = exp2f(m0 - mn0), al1 = exp2f(m1 - mn1);
        m0 = mn0; m1 = mn1;

        float sum0 = 0.f, sum1 = 0.f;
#pragma unroll
        for (int nt = 0; nt < 8; nt++) {
            s[nt][0] = exp2f(s[nt][0] - mn0); sum0 += s[nt][0];
            s[nt][1] = exp2f(s[nt][1] - mn0); sum0 += s[nt][1];
            s[nt][2] = exp2f(s[nt][2] - mn1); sum1 += s[nt][2];
            s[nt][3] = exp2f(s[nt][3] - mn1); sum1 += s[nt][3];
        }
#pragma unroll
        for (int off = 1; off < 4; off <<= 1) {
            sum0 += __shfl_xor_sync(0xffffffffu, sum0, off);
            sum1 += __shfl_xor_sync(0xffffffffu, sum1, off);
        }
        l0 = l0 * al0 + sum0;
        l1 = l1 * al1 + sum1;
#pragma unroll
        for (int nt = 0; nt < 8; nt++) {
            o[nt][0] *= al0; o[nt][1] *= al0;
            o[nt][2] *= al1; o[nt][3] *= al1;
        }

        // ---- P -> warp-private smem rows (fp16), then O += P @ V ----
#pragma unroll
        for (int nt = 0; nt < 8; nt++) {
            *(__half2*)&Ps[rowA * PH + 8 * nt + 2 * tg] =
                __floats2half2_rn(s[nt][0], s[nt][1]);
            *(__half2*)&Ps[rowB * PH + 8 * nt + 2 * tg] =
                __floats2half2_rn(s[nt][2], s[nt][3]);
        }
        __syncwarp();

#pragma unroll
        for (int kk = 0; kk < 4; kk++) {   // key chunks of 16
            uint32_t a[4];
            a[0] = *(const uint32_t*)&Ps[rowA * PH + 16 * kk + 2 * tg];
            a[1] = *(const uint32_t*)&Ps[rowB * PH + 16 * kk + 2 * tg];
            a[2] = *(const uint32_t*)&Ps[rowA * PH + 16 * kk + 2 * tg + 8];
            a[3] = *(const uint32_t*)&Ps[rowB * PH + 16 * kk + 2 * tg + 8];
#pragma unroll
            for (int nt = 0; nt < 8; nt++) {   // output d columns 8*nt..
                uint32_t bb[2];
                bb[0] = *(const uint32_t*)&Vt[(8 * nt + g) * PH + 16 * kk + 2 * tg];
                bb[1] = *(const uint32_t*)&Vt[(8 * nt + g) * PH + 16 * kk + 2 * tg + 8];
                mma_f16(o[nt], a, bb);
            }
        }
    }

    // Epilogue: normalize and store fp16 [B,T,C], head h at cols h*64.
    const float inv0 = 1.f / l0, inv1 = 1.f / l1;
    __half* obA = att + ((size_t)(b * T_) + q0 + rowA) * C_ + (size_t)h * D_;
    __half* obB = att + ((size_t)(b * T_) + q0 + rowB) * C_ + (size_t)h * D_;
#pragma unroll
    for (int nt = 0; nt < 8; nt++) {
        const int c = 8 * nt + 2 * tg;
        *(__half2*)(obA + c) = __floats2half2_rn(o[nt][0] * inv0, o[nt][1] * inv0);
        *(__half2*)(obB + c) = __floats2half2_rn(o[nt][2] * inv1, o[nt][3] * inv1);
    }
}

// ===========================================================================
// Launch
// ===========================================================================
extern "C" void kernel_launch(void* const* d_in, const int* in_sizes, int n_in,
                              void* d_out, int out_size) {
    const float* x      = (const float*)d_in[0];
    const float* w_qkv  = (const float*)d_in[1];
    const float* w_proj = (const float*)d_in[2];
    float* out = (float*)d_out;

    void *qkv_p, *att_p, *wqkvT_p, *wprojT_p;
    cudaGetSymbolAddress(&qkv_p, g_qkv);
    cudaGetSymbolAddress(&att_p, g_att);
    cudaGetSymbolAddress(&wqkvT_p, g_wqkvT);
    cudaGetSymbolAddress(&wprojT_p, g_wprojT);
    __half* qkv    = (__half*)qkv_p;
    __half* att    = (__half*)att_p;
    __half* wqkvT  = (__half*)wqkvT_p;
    __half* wprojT = (__half*)wprojT_p;

    cudaFuncSetAttribute(attn_mma, cudaFuncAttributeMaxDynamicSharedMemorySize,
                         ATT_SMEM);

    transposeK<<<dim3(N3_ / 32, KD_ / 32), dim3(32, 8)>>>(w_qkv, wqkvT, KD_, N3_);
    transposeK<<<dim3(C_ / 32, KD_ / 32), dim3(32, 8)>>>(w_proj, wprojT, KD_, C_);

    gemm_mma<float, __half><<<dim3(N3_ / 128, M_ / 128), 256>>>(x, wqkvT, qkv, N3_);
    attn_mma<<<dim3(T_ / QTILE, H_, B_), 256, ATT_SMEM>>>(qkv, att);
    gemm_mma<__half, float><<<dim3(C_ / 128, M_ / 128), 256>>>(att, wprojT, out, C_);
}

// round 15
// speedup vs baseline: 5.6820x; 1.1570x over previous
#include <cuda_runtime.h>
#include <cuda_fp16.h>
#include <cstdint>
#include <cstddef>

#define B_  4
#define T_  2048
#define C_  1024
#define H_  16
#define D_  64
#define M_  (B_ * T_)        // 8192
#define N3_ (3 * C_)         // 3072
#define KD_ 1024

// Scratch (static device globals — no allocation in kernel_launch).
__device__ __align__(16) __half g_qkv[(size_t)M_ * N3_];     // [B*T, 3C]
__device__ __align__(16) __half g_att[(size_t)M_ * C_];      // [B*T, C]
__device__ __align__(16) __half g_wqkvT[(size_t)N3_ * KD_];  // w_qkv^T  [N,K]
__device__ __align__(16) __half g_wprojT[(size_t)C_ * KD_];  // w_proj^T [N,K]

// mma.sync m16n8k16 fp16 with fp32 accumulate
__device__ __forceinline__ void mma_f16(float d[4], const uint32_t a[4],
                                        const uint32_t b[2]) {
    asm volatile(
        "mma.sync.aligned.m16n8k16.row.col.f32.f16.f16.f32 "
        "{%0,%1,%2,%3}, {%4,%5,%6,%7}, {%8,%9}, {%0,%1,%2,%3};"
        : "+f"(d[0]), "+f"(d[1]), "+f"(d[2]), "+f"(d[3])
        : "r"(a[0]), "r"(a[1]), "r"(a[2]), "r"(a[3]), "r"(b[0]), "r"(b[1]));
}

__device__ __forceinline__ void ldsm_x4(uint32_t& r0, uint32_t& r1,
                                        uint32_t& r2, uint32_t& r3,
                                        uint32_t addr) {
    asm volatile("ldmatrix.sync.aligned.m8n8.x4.shared.b16 {%0,%1,%2,%3}, [%4];"
                 : "=r"(r0), "=r"(r1), "=r"(r2), "=r"(r3) : "r"(addr));
}
__device__ __forceinline__ void ldsm_x4t(uint32_t& r0, uint32_t& r1,
                                         uint32_t& r2, uint32_t& r3,
                                         uint32_t addr) {
    asm volatile("ldmatrix.sync.aligned.m8n8.x4.trans.shared.b16 {%0,%1,%2,%3}, [%4];"
                 : "=r"(r0), "=r"(r1), "=r"(r2), "=r"(r3) : "r"(addr));
}
__device__ __forceinline__ uint32_t smem_u32(const void* p) {
    return (uint32_t)__cvta_generic_to_shared(p);
}

// ===========================================================================
// FP16 tensor-core GEMM with ldmatrix fragments (unchanged from passing R14).
// ===========================================================================
#define PHG 40            // pitch in halves
#define NSTAGE (KD_ / 32) // 32
#define GBUF (128 * PHG * 2)  // bytes per buffer

template <typename TA, typename TC>
__global__ __launch_bounds__(256, 2)
void gemm_mma(const TA* __restrict__ A, const __half* __restrict__ BT,
              TC* __restrict__ Cm, int N) {
    __shared__ __half As[2][128][PHG];
    __shared__ __half Bs[2][128][PHG];

    const int tid = threadIdx.x;
    const int lane = tid & 31, wid = tid >> 5;
    const int g = lane >> 2, tg = lane & 3;
    const int wm = (wid & 1) * 64;
    const int wn = (wid >> 1) * 32;
    const int rowBase = blockIdx.y * 128;
    const int colBase = blockIdx.x * 128;

    const uint32_t as_u = smem_u32(&As[0][0][0]);
    const uint32_t bs_u = smem_u32(&Bs[0][0][0]);
    const uint32_t aOff =
        ((wm + (lane & 15)) * PHG + 8 * ((lane >> 4) & 1)) * 2;
    const uint32_t bOff =
        ((wn + (lane & 7) + ((lane & 16) >> 1)) * PHG + ((lane & 8) ? 8 : 0)) * 2;

    const int rowL = tid >> 1;           // 0..127
    const int cbL  = (tid & 1) * 16;     // 0 or 16
    const __half* Bp = BT + (size_t)(colBase + rowL) * KD_ + cbL;
    const float* Apf = nullptr;
    const __half* Aph = nullptr;
    if constexpr (sizeof(TA) == 4)
        Apf = (const float*)A + (size_t)(rowBase + (tid >> 3)) * KD_ + ((tid & 7) << 2);
    else
        Aph = (const __half*)A + (size_t)(rowBase + rowL) * KD_ + cbL;

    float d[4][4][4];
#pragma unroll
    for (int mt = 0; mt < 4; mt++)
#pragma unroll
        for (int nt = 0; nt < 4; nt++)
#pragma unroll
            for (int q = 0; q < 4; q++) d[mt][nt][q] = 0.f;

    float4 pa[4];
    uint4 ua0, ua1, ub0, ub1;

#define LDG_STAGE(kt)                                                          \
    do {                                                                       \
        if constexpr (sizeof(TA) == 4) {                                       \
            _Pragma("unroll")                                                  \
            for (int e = 0; e < 4; e++)                                        \
                pa[e] = *(const float4*)(Apf + (size_t)(e * 32) * KD_ + (kt) * 32); \
        } else {                                                               \
            ua0 = *(const uint4*)(Aph + (kt) * 32);                            \
            ua1 = *(const uint4*)(Aph + (kt) * 32 + 8);                        \
        }                                                                      \
        ub0 = *(const uint4*)(Bp + (kt) * 32);                                 \
        ub1 = *(const uint4*)(Bp + (kt) * 32 + 8);                             \
    } while (0)

#define STS_STAGE(buf)                                                        \
    do {                                                                      \
        if constexpr (sizeof(TA) == 4) {                                      \
            _Pragma("unroll")                                                 \
            for (int e = 0; e < 4; e++) {                                     \
                __half2* ap = (__half2*)&As[buf][(tid >> 3) + e * 32][(tid & 7) << 2]; \
                ap[0] = __floats2half2_rn(pa[e].x, pa[e].y);                  \
                ap[1] = __floats2half2_rn(pa[e].z, pa[e].w);                  \
            }                                                                 \
        } else {                                                              \
            *(uint4*)&As[buf][rowL][cbL] = ua0;                               \
            *(uint4*)&As[buf][rowL][cbL + 8] = ua1;                           \
        }                                                                     \
        *(uint4*)&Bs[buf][rowL][cbL] = ub0;                                   \
        *(uint4*)&Bs[buf][rowL][cbL + 8] = ub1;                               \
    } while (0)

    LDG_STAGE(0);
    STS_STAGE(0);

    for (int kt = 0; kt < NSTAGE; kt++) {
        __syncthreads();
        const int buf = kt & 1;
        const uint32_t abase = as_u + buf * GBUF;
        const uint32_t bbase = bs_u + buf * GBUF;
        if (kt + 1 < NSTAGE) LDG_STAGE(kt + 1);

#pragma unroll
        for (int kk = 0; kk < 2; kk++) {
            uint32_t af[4][4], bf[4][2];
#pragma unroll
            for (int mt = 0; mt < 4; mt++)
                ldsm_x4(af[mt][0], af[mt][1], af[mt][2], af[mt][3],
                        abase + aOff + mt * (16 * PHG * 2) + kk * 32);
#pragma unroll
            for (int p = 0; p < 2; p++)
                ldsm_x4(bf[2 * p][0], bf[2 * p][1], bf[2 * p + 1][0], bf[2 * p + 1][1],
                        bbase + bOff + p * (16 * PHG * 2) + kk * 32);
#pragma unroll
            for (int mt = 0; mt < 4; mt++)
#pragma unroll
                for (int nt = 0; nt < 4; nt++)
                    mma_f16(d[mt][nt], af[mt], bf[nt]);
        }

        if (kt + 1 < NSTAGE) {
            __syncthreads();
            STS_STAGE(buf ^ 1);
        }
    }

#pragma unroll
    for (int mt = 0; mt < 4; mt++) {
        const int r = rowBase + wm + mt * 16 + g;
#pragma unroll
        for (int nt = 0; nt < 4; nt++) {
            const int c = colBase + wn + nt * 8 + 2 * tg;
            if constexpr (sizeof(TC) == 4) {
                float* p = (float*)Cm + (size_t)r * N + c;
                *(float2*)p = make_float2(d[mt][nt][0], d[mt][nt][1]);
                *(float2*)(p + (size_t)8 * N) =
                    make_float2(d[mt][nt][2], d[mt][nt][3]);
            } else {
                __half* p = (__half*)Cm + (size_t)r * N + c;
                *(__half2*)p = __floats2half2_rn(d[mt][nt][0], d[mt][nt][1]);
                *(__half2*)(p + (size_t)8 * N) =
                    __floats2half2_rn(d[mt][nt][2], d[mt][nt][3]);
            }
        }
    }
#undef LDG_STAGE
#undef STS_STAGE
}

// ===========================================================================
// Transpose + fp16 convert: out[c][r] = half(in[r][c])
// ===========================================================================
__global__ void transposeK(const float* __restrict__ in, __half* __restrict__ out,
                           int R, int Cc) {
    __shared__ float t[32][33];
    const int c0 = blockIdx.x * 32, r0 = blockIdx.y * 32;
    const int tx = threadIdx.x, ty = threadIdx.y;
#pragma unroll
    for (int i = 0; i < 32; i += 8)
        t[ty + i][tx] = in[(size_t)(r0 + ty + i) * Cc + c0 + tx];
    __syncthreads();
#pragma unroll
    for (int i = 0; i < 32; i += 8)
        out[(size_t)(c0 + ty + i) * R + r0 + tx] = __float2half_rn(t[tx][ty + i]);
}

// ===========================================================================
// FP16 flash attention with ldmatrix fragment loads (single delta vs R14).
// CTA = 128 queries x (b,h), 8 warps x 16 q-rows. KV tile 64.
// Q/K/P fragments via ldmatrix.x4; V stays KEY-MAJOR, PV B-fragments via
// ldmatrix.x4.trans (kills the 16-scalar-STS V transpose).
// PH=72: ldmatrix row banks 4r mod 32 -> conflict-free.
// Lane maps re-derived and verified against the R11/R14 scalar fragments.
// ===========================================================================
#define QTILE 128
#define KTILE 64
#define PH 72   // pitch in halves for all tiles
#define ATT_SMEM ((QTILE * PH + KTILE * PH + KTILE * PH + QTILE * PH) * 2)

__global__ __launch_bounds__(256, 2)
void attn_mma(const __half* __restrict__ qkv, __half* __restrict__ att) {
    extern __shared__ __half smh[];
    __half* Qs = smh;                     // [128][72]  q-major
    __half* Ks = Qs + QTILE * PH;         // [64][72]   key-major
    __half* Vs = Ks + KTILE * PH;         // [64][72]   key-major
    __half* Ps = Vs + KTILE * PH;         // [128][72]  q-major

    const int qt = (int)gridDim.x - 1 - (int)blockIdx.x;  // heavy tiles first
    const int h = blockIdx.y, b = blockIdx.z;
    const int q0 = qt * QTILE;
    const int tid = threadIdx.x;
    const int lane = tid & 31, w = tid >> 5;
    const int g = lane >> 2, tg = lane & 3;

    const uint32_t qs_u = smem_u32(Qs);
    const uint32_t ks_u = smem_u32(Ks);
    const uint32_t vs_u = smem_u32(Vs);
    const uint32_t ps_u = smem_u32(Ps);

    // ldmatrix per-lane byte offsets.
    // A-frag (Qs/Ps rows 16w..16w+15): lanes 0-15 rows, lanes 16-31 k+8.
    const uint32_t aRowOff =
        ((16 * w + (lane & 15)) * PH + 8 * ((lane >> 4) & 1)) * 2;
    // K B-frag: matrices (keys0-7,k0-7),(keys0-7,k8-15),(keys8-15,k0-7),(keys8-15,k8-15)
    const uint32_t bKOff =
        (((lane & 7) + ((lane & 16) >> 1)) * PH + ((lane & 8) ? 8 : 0)) * 2;
    // V trans-frag: matrices (keys0-7,d0-7),(keys8-15,d0-7),(keys0-7,d8-15),(keys8-15,d8-15)
    const uint32_t vOff =
        ((lane & 15) * PH + ((lane >> 4) & 1) * 8) * 2;

    const __half* base = qkv + (size_t)b * T_ * N3_ + (size_t)h * D_;
    const __half* qb = base;
    const __half* kb = base + C_;
    const __half* vb = base + 2 * C_;

    // Load Q tile [128 x 64] = 1024 uint4 -> 4 per thread (8 halves each)
#pragma unroll
    for (int e = 0; e < 4; e++) {
        int i4 = e * 256 + tid;
        int r = i4 >> 3, sg = (i4 & 7) << 3;
        *(uint4*)&Qs[r * PH + sg] = *(const uint4*)&qb[(size_t)(q0 + r) * N3_ + sg];
    }

    float o[8][4];
#pragma unroll
    for (int nt = 0; nt < 8; nt++)
#pragma unroll
        for (int q = 0; q < 4; q++) o[nt][q] = 0.f;
    float m0 = -1e30f, m1 = -1e30f, l0 = 0.f, l1 = 0.f;

    const int rowA = 16 * w + g;
    const int rowB = rowA + 8;
    const float SC = 0.125f * 1.44269504089f;   // scale * log2(e)
    const int ntiles = 2 * qt + 2;

    for (int jt = 0; jt < ntiles; jt++) {
        const int k0 = jt * KTILE;
        __syncthreads();   // prior iter's K/V reads done (Q stores visible)

        // K and V tiles [64x64] key-major — 2 uint4 each per thread.
#pragma unroll
        for (int e = 0; e < 2; e++) {
            int i4 = e * 256 + tid;
            int r = i4 >> 3, sg = (i4 & 7) << 3;
            *(uint4*)&Ks[r * PH + sg] = *(const uint4*)&kb[(size_t)(k0 + r) * N3_ + sg];
            *(uint4*)&Vs[r * PH + sg] = *(const uint4*)&vb[(size_t)(k0 + r) * N3_ + sg];
        }
        __syncthreads();

        // ---- S = Q @ K^T (16 x 64 per warp) via ldmatrix + mma ----
        float s[8][4];
#pragma unroll
        for (int nt = 0; nt < 8; nt++)
#pragma unroll
            for (int q = 0; q < 4; q++) s[nt][q] = 0.f;

#pragma unroll
        for (int kk = 0; kk < 4; kk++) {
            uint32_t a[4];
            ldsm_x4(a[0], a[1], a[2], a[3], qs_u + aRowOff + kk * 32);
#pragma unroll
            for (int p = 0; p < 4; p++) {    // key blocks of 16 (nt = 2p, 2p+1)
                uint32_t b0, b1, b2, b3;
                ldsm_x4(b0, b1, b2, b3,
                        ks_u + bKOff + p * (16 * PH * 2) + kk * 32);
                uint32_t bl[2] = {b0, b1}, bh[2] = {b2, b3};
                mma_f16(s[2 * p], a, bl);
                mma_f16(s[2 * p + 1], a, bh);
            }
        }

        // ---- softmax (registers, exp2 domain, quad reductions) ----
        const bool masked = (jt >= 2 * qt);
        const int qr0 = q0 + rowA, qr1 = q0 + rowB;
        float rm0 = -1e30f, rm1 = -1e30f;
#pragma unroll
        for (int nt = 0; nt < 8; nt++) {
            const int key = k0 + 8 * nt + 2 * tg;
            s[nt][0] *= SC; s[nt][1] *= SC;
            s[nt][2] *= SC; s[nt][3] *= SC;
            if (masked) {
                if (key     > qr0) s[nt][0] = -1e30f;
                if (key + 1 > qr0) s[nt][1] = -1e30f;
                if (key     > qr1) s[nt][2] = -1e30f;
                if (key + 1 > qr1) s[nt][3] = -1e30f;
            }
            rm0 = fmaxf(rm0, fmaxf(s[nt][0], s[nt][1]));
            rm1 = fmaxf(rm1, fmaxf(s[nt][2], s[nt][3]));
        }
#pragma unroll
        for (int off = 1; off < 4; off <<= 1) {
            rm0 = fmaxf(rm0, __shfl_xor_sync(0xffffffffu, rm0, off));
            rm1 = fmaxf(rm1, __shfl_xor_sync(0xffffffffu, rm1, off));
        }
        const float mn0 = fmaxf(m0, rm0), mn1 = fmaxf(m1, rm1);
        const float al0 = exp2f(m0 - mn0), al1 = exp2f(m1 - mn1);
        m0 = mn0; m1 = mn1;

        float sum0 = 0.f, sum1 = 0.f;
#pragma unroll
        for (int nt = 0; nt < 8; nt++) {
            s[nt][0] = exp2f(s[nt][0] - mn0); sum0 += s[nt][0];
            s[nt][1] = exp2f(s[nt][1] - mn0); sum0 += s[nt][1];
            s[nt][2] = exp2f(s[nt][2] - mn1); sum1 += s[nt][2];
            s[nt][3] = exp2f(s[nt][3] - mn1); sum1 += s[nt][3];
        }
#pragma unroll
        for (int off = 1; off < 4; off <<= 1) {
            sum0 += __shfl_xor_sync(0xffffffffu, sum0, off);
            sum1 += __shfl_xor_sync(0xffffffffu, sum1, off);
        }
        l0 = l0 * al0 + sum0;
        l1 = l1 * al1 + sum1;
#pragma unroll
        for (int nt = 0; nt < 8; nt++) {
            o[nt][0] *= al0; o[nt][1] *= al0;
            o[nt][2] *= al1; o[nt][3] *= al1;
        }

        // ---- P -> warp-private smem rows (fp16), then O += P @ V ----
#pragma unroll
        for (int nt = 0; nt < 8; nt++) {
            *(__half2*)&Ps[rowA * PH + 8 * nt + 2 * tg] =
                __floats2half2_rn(s[nt][0], s[nt][1]);
            *(__half2*)&Ps[rowB * PH + 8 * nt + 2 * tg] =
                __floats2half2_rn(s[nt][2], s[nt][3]);
        }
        __syncwarp();

#pragma unroll
        for (int kk = 0; kk < 4; kk++) {   // key chunks of 16
            uint32_t a[4];
            ldsm_x4(a[0], a[1], a[2], a[3], ps_u + aRowOff + kk * 32);
#pragma unroll
            for (int p = 0; p < 2; p++) {  // d blocks of 16 (nt = 2p..2p+1 per half)
                uint32_t b0, b1, b2, b3;
                ldsm_x4t(b0, b1, b2, b3,
                         vs_u + vOff + kk * (16 * PH * 2) + p * 32);
                uint32_t bl[2] = {b0, b1}, bh[2] = {b2, b3};
                mma_f16(o[4 * p], a, bl);        // d cols 16p+0..7
                mma_f16(o[4 * p + 1], a, bh);    // d cols 16p+8..15
            }
            // d blocks 32..63
#pragma unroll
            for (int p = 2; p < 4; p++) {
                uint32_t b0, b1, b2, b3;
                ldsm_x4t(b0, b1, b2, b3,
                         vs_u + vOff + kk * (16 * PH * 2) + p * 32);
                uint32_t bl[2] = {b0, b1}, bh[2] = {b2, b3};
                mma_f16(o[4 * (p - 2) + 2], a, bl);  // d cols 16p+0..7
                mma_f16(o[4 * (p - 2) + 3], a, bh);  // d cols 16p+8..15
            }
        }
    }

    // Epilogue: normalize and store fp16 [B,T,C], head h at cols h*64.
    // o-index mapping from PV: o[4p+q] covers d block 16p+8q.. wait —
    // mapping used above: o[0]=d0-7, o[1]=d8-15, o[2]=d32-39, o[3]=d40-47,
    // o[4]=d16-23, o[5]=d24-31, o[6]=d48-55, o[7]=d56-63.
    const int dcol[8] = {0, 8, 32, 40, 16, 24, 48, 56};
    const float inv0 = 1.f / l0, inv1 = 1.f / l1;
    __half* obA = att + ((size_t)(b * T_) + q0 + rowA) * C_ + (size_t)h * D_;
    __half* obB = att + ((size_t)(b * T_) + q0 + rowB) * C_ + (size_t)h * D_;
#pragma unroll
    for (int nt = 0; nt < 8; nt++) {
        const int c = dcol[nt] + 2 * tg;
        *(__half2*)(obA + c) = __floats2half2_rn(o[nt][0] * inv0, o[nt][1] * inv0);
        *(__half2*)(obB + c) = __floats2half2_rn(o[nt][2] * inv1, o[nt][3] * inv1);
    }
}

// ===========================================================================
// Launch
// ===========================================================================
extern "C" void kernel_launch(void* const* d_in, const int* in_sizes, int n_in,
                              void* d_out, int out_size) {
    const float* x      = (const float*)d_in[0];
    const float* w_qkv  = (const float*)d_in[1];
    const float* w_proj = (const float*)d_in[2];
    float* out = (float*)d_out;

    void *qkv_p, *att_p, *wqkvT_p, *wprojT_p;
    cudaGetSymbolAddress(&qkv_p, g_qkv);
    cudaGetSymbolAddress(&att_p, g_att);
    cudaGetSymbolAddress(&wqkvT_p, g_wqkvT);
    cudaGetSymbolAddress(&wprojT_p, g_wprojT);
    __half* qkv    = (__half*)qkv_p;
    __half* att    = (__half*)att_p;
    __half* wqkvT  = (__half*)wqkvT_p;
    __half* wprojT = (__half*)wprojT_p;

    cudaFuncSetAttribute(attn_mma, cudaFuncAttributeMaxDynamicSharedMemorySize,
                         ATT_SMEM);

    transposeK<<<dim3(N3_ / 32, KD_ / 32), dim3(32, 8)>>>(w_qkv, wqkvT, KD_, N3_);
    transposeK<<<dim3(C_ / 32, KD_ / 32), dim3(32, 8)>>>(w_proj, wprojT, KD_, C_);

    gemm_mma<float, __half><<<dim3(N3_ / 128, M_ / 128), 256>>>(x, wqkvT, qkv, N3_);
    attn_mma<<<dim3(T_ / QTILE, H_, B_), 256, ATT_SMEM>>>(qkv, att);
    gemm_mma<__half, float><<<dim3(C_ / 128, M_ / 128), 256>>>(att, wprojT, out, C_);
}